// round 1
// baseline (speedup 1.0000x reference)
#include <cuda_runtime.h>
#include <cstdint>

#define BATCH 128
#define N0 2048
#define N1 2048
#define N2 512
#define K0 1024
#define K1 2048
#define K2 2048
#define ALPHA_C 0.9f
#define BETA_C  0.85f
#define TSTEPS 50

// ---------------- scratch (static device allocations; no cudaMalloc) ----------------
__device__ float g_H0[BATCH * N0];          // constant input drive (inputs @ W0)
__device__ float g_m0[BATCH * N0];          // layer0 membrane
__device__ float g_s1[BATCH * N1];          // layer1 synapse
__device__ float g_m1[BATCH * N1];          // layer1 membrane
__device__ float g_spk0[BATCH * N0];        // layer0 spikes (0.0/1.0)
__device__ float g_spk1[BATCH * N1];        // layer1 spikes (0.0/1.0)
__device__ float g_s2[BATCH * N2];          // layer2 synapse
__device__ float g_m2[BATCH * N2];          // layer2 membrane (final output)
__device__ float g_p1[16 * BATCH * N1];     // split-K partials for GEMM0/GEMM1
__device__ float g_p2[16 * BATCH * N2];     // split-K partials for GEMM2

// ---------------- split-K GEMM: P[ks][b][j] = sum_{i in chunk ks} A[b][i] * W[i][j] ----------------
// A: [BATCH][KTOT] row-major, W: [KTOT][N] row-major.
// Block: T threads, each thread owns 4 consecutive j (float4) and BT batch rows.
template <int N, int KTOT, int CHUNK, int BT, int T>
__global__ void __launch_bounds__(T) gemm_partial(const float* __restrict__ A,
                                                  const float* __restrict__ W,
                                                  float* __restrict__ P)
{
    __shared__ float As[BT][CHUNK];
    const int jt = blockIdx.x;
    const int bt = blockIdx.y;
    const int ks = blockIdx.z;
    const int j0 = jt * (T * 4) + threadIdx.x * 4;
    const int b0 = bt * BT;
    const int k0 = ks * CHUNK;

    // stage A tile (spike values or input activations) into smem, coalesced
    for (int x = threadIdx.x; x < BT * CHUNK; x += T) {
        int bb = x / CHUNK;
        int ii = x - bb * CHUNK;
        As[bb][ii] = A[(size_t)(b0 + bb) * KTOT + k0 + ii];
    }
    __syncthreads();

    float4 acc[BT];
#pragma unroll
    for (int b = 0; b < BT; b++) acc[b] = make_float4(0.f, 0.f, 0.f, 0.f);

    const float* Wp = W + (size_t)k0 * N + j0;
#pragma unroll 2
    for (int i = 0; i < CHUNK; i++) {
        float4 w = *(const float4*)(Wp + (size_t)i * N);
#pragma unroll
        for (int b = 0; b < BT; b++) {
            float a = As[b][i];
            acc[b].x += a * w.x;
            acc[b].y += a * w.y;
            acc[b].z += a * w.z;
            acc[b].w += a * w.w;
        }
    }

#pragma unroll
    for (int b = 0; b < BT; b++) {
        *(float4*)(P + ((size_t)ks * BATCH + b0 + b) * N + j0) = acc[b];
    }
}

// ---------------- helpers ----------------
__device__ __forceinline__ float4 f4_zero() { return make_float4(0.f, 0.f, 0.f, 0.f); }

__device__ __forceinline__ void f4_add(float4& a, const float4 b) {
    a.x += b.x; a.y += b.y; a.z += b.z; a.w += b.w;
}
__device__ __forceinline__ float4 f4_axpy(float alpha, const float4 a, const float4 b) {
    // alpha*a + b
    return make_float4(fmaf(alpha, a.x, b.x), fmaf(alpha, a.y, b.y),
                       fmaf(alpha, a.z, b.z), fmaf(alpha, a.w, b.w));
}
// spike = (m - 1 > 0); membrane hard-reset to 0 where spiked
__device__ __forceinline__ void lif_spike_reset(float4& m, float4& spk) {
    bool fx = (m.x - 1.0f) > 0.0f;
    bool fy = (m.y - 1.0f) > 0.0f;
    bool fz = (m.z - 1.0f) > 0.0f;
    bool fw = (m.w - 1.0f) > 0.0f;
    spk.x = fx ? 1.0f : 0.0f; if (fx) m.x = 0.0f;
    spk.y = fy ? 1.0f : 0.0f; if (fy) m.y = 0.0f;
    spk.z = fz ? 1.0f : 0.0f; if (fz) m.z = 0.0f;
    spk.w = fw ? 1.0f : 0.0f; if (fw) m.w = 0.0f;
}

// ---------------- zero persistent state ----------------
__global__ void init_states()
{
    int idx = blockIdx.x * blockDim.x + threadIdx.x;   // < 65536
    float4 z = f4_zero();
    ((float4*)g_s1)[idx] = z;
    ((float4*)g_m1)[idx] = z;
    if (idx < BATCH * N2 / 4) {
        ((float4*)g_s2)[idx] = z;
        ((float4*)g_m2)[idx] = z;
    }
}

// ---------------- H0 = sum of 8 partials; then layer0 step-0 update ----------------
__global__ void reduce0()
{
    int idx = blockIdx.x * blockDim.x + threadIdx.x;   // < 65536 float4 units
    float4 h = f4_zero();
#pragma unroll
    for (int ks = 0; ks < 8; ks++)
        f4_add(h, ((const float4*)g_p1)[(size_t)ks * (BATCH * N0 / 4) + idx]);
    ((float4*)g_H0)[idx] = h;
    // step 0: m0 = beta*0 + H0 = H0
    float4 m = h;
    float4 spk;
    lif_spike_reset(m, spk);
    ((float4*)g_m0)[idx]   = m;
    ((float4*)g_spk0)[idx] = spk;
}

// ---------------- reduce GEMM1 partials + layer1 LIF update -> spk1 ----------------
__global__ void reduce1()
{
    int idx = blockIdx.x * blockDim.x + threadIdx.x;   // < 65536
    float4 h = f4_zero();
#pragma unroll
    for (int ks = 0; ks < 16; ks++)
        f4_add(h, ((const float4*)g_p1)[(size_t)ks * (BATCH * N1 / 4) + idx]);
    float4 s = ((float4*)g_s1)[idx];
    s = f4_axpy(ALPHA_C, s, h);                 // s1 = alpha*s1 + h1
    float4 m = ((float4*)g_m1)[idx];
    m = f4_axpy(BETA_C, m, s);                  // m1 = beta*m1 + s1
    float4 spk;
    lif_spike_reset(m, spk);
    ((float4*)g_s1)[idx]   = s;
    ((float4*)g_m1)[idx]   = m;
    ((float4*)g_spk1)[idx] = spk;
}

// ---------------- reduce GEMM2 partials + layer2 update; also layer0 update for next step ----------------
__global__ void reduce2_l0()
{
    int gid = blockIdx.x * blockDim.x + threadIdx.x;
    const int n2 = BATCH * N2 / 4;              // 16384
    if (gid < n2) {
        float4 h = f4_zero();
#pragma unroll
        for (int ks = 0; ks < 16; ks++)
            f4_add(h, ((const float4*)g_p2)[(size_t)ks * n2 + gid]);
        float4 s = ((float4*)g_s2)[gid];
        s = f4_axpy(ALPHA_C, s, h);             // s2 = alpha*s2 + h2
        float4 m = ((float4*)g_m2)[gid];
        m = f4_axpy(BETA_C, m, s);              // m2 = beta*m2 + s2  (no reset)
        ((float4*)g_s2)[gid] = s;
        ((float4*)g_m2)[gid] = m;
    } else {
        int idx = gid - n2;                      // < 65536
        float4 m = ((float4*)g_m0)[idx];
        float4 h = ((float4*)g_H0)[idx];
        m = f4_axpy(BETA_C, m, h);              // m0 = beta*m0 + H0 (s0 = H0 always)
        float4 spk;
        lif_spike_reset(m, spk);
        ((float4*)g_m0)[idx]   = m;
        ((float4*)g_spk0)[idx] = spk;
    }
}

__global__ void copy_out(float* __restrict__ out)
{
    int idx = blockIdx.x * blockDim.x + threadIdx.x;   // < 16384
    ((float4*)out)[idx] = ((const float4*)g_m2)[idx];
}

// ---------------- launch ----------------
extern "C" void kernel_launch(void* const* d_in, const int* in_sizes, int n_in,
                              void* d_out, int out_size)
{
    const float* inp = nullptr;
    const float* W0  = nullptr;
    const float* W1  = nullptr;
    const float* W2  = nullptr;
    for (int i = 0; i < n_in; i++) {
        switch (in_sizes[i]) {
            case BATCH * K0: inp = (const float*)d_in[i]; break;   // 131072
            case K0 * N0:    W0  = (const float*)d_in[i]; break;   // 2097152
            case K1 * N1:    W1  = (const float*)d_in[i]; break;   // 4194304
            case K2 * N2:    W2  = (const float*)d_in[i]; break;   // 1048576
        }
    }

    float *p1, *p2, *spk0, *spk1;
    cudaGetSymbolAddress((void**)&p1,   g_p1);
    cudaGetSymbolAddress((void**)&p2,   g_p2);
    cudaGetSymbolAddress((void**)&spk0, g_spk0);
    cudaGetSymbolAddress((void**)&spk1, g_spk1);

    // zero persistent state
    init_states<<<256, 256>>>();

    // H0 = inputs @ W0 (once), then step-0 layer0 update
    gemm_partial<N0, K0, 128, 16, 256><<<dim3(2, 8, 8), 256>>>(inp, W0, p1);
    reduce0<<<256, 256>>>();

    for (int t = 0; t < TSTEPS; t++) {
        // h1 = spk0 @ W1 ; layer1 update -> spk1
        gemm_partial<N1, K1, 128, 16, 256><<<dim3(2, 8, 16), 256>>>(spk0, W1, p1);
        reduce1<<<256, 256>>>();
        // h2 = spk1 @ W2 ; layer2 update ; also layer0 update for step t+1
        gemm_partial<N2, K2, 128, 16, 128><<<dim3(1, 8, 16), 128>>>(spk1, W2, p2);
        reduce2_l0<<<320, 256>>>();
    }

    copy_out<<<64, 256>>>((float*)d_out);
}

// round 3
// speedup vs baseline: 2.3583x; 2.3583x over previous
#include <cuda_runtime.h>
#include <cuda_fp16.h>
#include <cstdint>

#define BATCH 128
#define N0 2048
#define N1 2048
#define N2 512
#define K0 1024
#define KF 4096            // hi|lo concatenated K dimension
#define ALPHA_C 0.9f
#define BETA_C  0.85f
#define TSTEPS 50

// ---------------- static device scratch ----------------
__device__ float g_H0[BATCH * N0];
__device__ float g_m0[BATCH * N0];
__device__ float g_s1[BATCH * N1];
__device__ float g_m1[BATCH * N1];
__device__ float g_s2[BATCH * N2];
__device__ float g_m2[BATCH * N2];
__device__ __half g_spk0h[BATCH * KF];     // layer0 spikes fp16, duplicated [m][k]=[m][k+2048]
__device__ __half g_spk1h[BATCH * KF];     // layer1 spikes fp16, duplicated
__device__ __half g_W1Th[N1 * KF];         // [n][k]: k<2048 hi(W1[k][n]), k>=2048 lo
__device__ __half g_W2Th[N2 * KF];
__device__ float g_p1[8 * BATCH * N1];     // split-K partials GEMM0/GEMM1
__device__ float g_p2[16 * BATCH * N2];    // split-K partials GEMM2

// ---------------- PTX helpers ----------------
__device__ __forceinline__ uint32_t smem_u32(const void* p) {
    uint32_t a;
    asm("{ .reg .u64 t; cvta.to.shared.u64 t, %1; cvt.u32.u64 %0, t; }" : "=r"(a) : "l"(p));
    return a;
}
__device__ __forceinline__ void cp16(uint32_t dst, const void* src) {
    asm volatile("cp.async.cg.shared.global [%0], [%1], 16;" :: "r"(dst), "l"(src));
}
__device__ __forceinline__ void ldmx4(uint32_t addr, uint32_t& r0, uint32_t& r1,
                                      uint32_t& r2, uint32_t& r3) {
    asm volatile("ldmatrix.sync.aligned.m8n8.x4.shared.b16 {%0,%1,%2,%3}, [%4];"
                 : "=r"(r0), "=r"(r1), "=r"(r2), "=r"(r3) : "r"(addr));
}
__device__ __forceinline__ void mma16816(float* d, const uint32_t* a, const uint32_t* b) {
    asm volatile(
        "mma.sync.aligned.m16n8k16.row.col.f32.f16.f16.f32 "
        "{%0,%1,%2,%3}, {%4,%5,%6,%7}, {%8,%9}, {%0,%1,%2,%3};"
        : "+f"(d[0]), "+f"(d[1]), "+f"(d[2]), "+f"(d[3])
        : "r"(a[0]), "r"(a[1]), "r"(a[2]), "r"(a[3]), "r"(b[0]), "r"(b[1]));
}

// ---------------- HMMA split-K GEMM ----------------
// P[ks][m][n0..n0+127] = A[128, KF] @ B[n][k]^T over k in [ks*KLOC, (ks+1)*KLOC)
// A: spikes fp16 [128][4096] (duplicated), B: weight hi/lo fp16 [NFULL][4096].
// 256 threads: warps 4(M) x 2(N); warp tile 32x64.
#define RS 40   // smem row stride in halves (80B) -> conflict-free ldmatrix

template <int KLOC, int NFULL>
__global__ void __launch_bounds__(256) gemm_mma(const __half* __restrict__ A,
                                                const __half* __restrict__ B,
                                                float* __restrict__ P)
{
    __shared__ __align__(128) __half sA[2][128 * RS];
    __shared__ __align__(128) __half sB[2][128 * RS];
    constexpr int S = KLOC / 32;

    const int tid = threadIdx.x, lane = tid & 31, wid = tid >> 5;
    const int wm = wid & 3, wn = wid >> 2;
    const int n0 = blockIdx.x * 128;
    const int kbase = blockIdx.y * KLOC;

    float acc[2][8][4];
    #pragma unroll
    for (int mt = 0; mt < 2; mt++)
        #pragma unroll
        for (int nt = 0; nt < 8; nt++)
            #pragma unroll
            for (int q = 0; q < 4; q++) acc[mt][nt][q] = 0.f;

    auto load_stage = [&](int s) {
        const int buf = s & 1;
        const int k0 = kbase + s * 32;
        #pragma unroll
        for (int c = tid; c < 512; c += 256) {           // A: 128 rows x 4 16B chunks
            int r = c >> 2, sub = c & 3;
            cp16(smem_u32(&sA[buf][r * RS + sub * 8]), A + (size_t)r * KF + k0 + sub * 8);
        }
        #pragma unroll
        for (int c = tid; c < 512; c += 256) {           // B: 128 n-rows x 4 chunks
            int r = c >> 2, sub = c & 3;
            cp16(smem_u32(&sB[buf][r * RS + sub * 8]), B + (size_t)(n0 + r) * KF + k0 + sub * 8);
        }
        asm volatile("cp.async.commit_group;" ::: "memory");
    };

    load_stage(0);

    for (int s = 0; s < S; s++) {
        if (s + 1 < S) {
            load_stage(s + 1);
            asm volatile("cp.async.wait_group 1;" ::: "memory");
        } else {
            asm volatile("cp.async.wait_group 0;" ::: "memory");
        }
        __syncthreads();
        const __half* bufA = sA[s & 1];
        const __half* bufB = sB[s & 1];
        #pragma unroll
        for (int ks = 0; ks < 2; ks++) {                 // two k16 steps per 32-k stage
            uint32_t a[2][4], b[8][2];
            #pragma unroll
            for (int mt = 0; mt < 2; mt++) {             // A frags: rows wm*32+mt*16
                int row = wm * 32 + mt * 16 + (lane & 15);
                uint32_t ad = smem_u32(bufA + row * RS + ks * 16 + (lane >> 4) * 8);
                ldmx4(ad, a[mt][0], a[mt][1], a[mt][2], a[mt][3]);
            }
            #pragma unroll
            for (int q = 0; q < 4; q++) {                // B frags: n octets 2q, 2q+1
                int nr = wn * 64 + q * 16 + (lane >> 4) * 8 + (lane & 7);
                uint32_t bd = smem_u32(bufB + nr * RS + ks * 16 + ((lane >> 3) & 1) * 8);
                ldmx4(bd, b[2 * q][0], b[2 * q][1], b[2 * q + 1][0], b[2 * q + 1][1]);
            }
            #pragma unroll
            for (int mt = 0; mt < 2; mt++)
                #pragma unroll
                for (int nt = 0; nt < 8; nt++)
                    mma16816(acc[mt][nt], a[mt], b[nt]);
        }
        __syncthreads();                                 // buffer reuse fence
    }

    // epilogue: write split-K partials
    float* Pb = P + (size_t)blockIdx.y * BATCH * NFULL + n0;
    #pragma unroll
    for (int mt = 0; mt < 2; mt++) {
        int r = wm * 32 + mt * 16 + (lane >> 2);
        #pragma unroll
        for (int nt = 0; nt < 8; nt++) {
            int cc = wn * 64 + nt * 8 + (lane & 3) * 2;
            *(float2*)(Pb + (size_t)r * NFULL + cc)       = make_float2(acc[mt][nt][0], acc[mt][nt][1]);
            *(float2*)(Pb + (size_t)(r + 8) * NFULL + cc) = make_float2(acc[mt][nt][2], acc[mt][nt][3]);
        }
    }
}

// ---------------- weight transpose + fp16 hi/lo split (once per launch) ----------------
__global__ void conv_transpose(const float* __restrict__ W, __half* __restrict__ WT)
{
    __shared__ float t[32][33];
    const int k0 = blockIdx.x * 32, nb = blockIdx.y * 32;
    const int N = gridDim.y * 32;
    for (int i = threadIdx.y; i < 32; i += 8)
        t[i][threadIdx.x] = W[(size_t)(k0 + i) * N + nb + threadIdx.x];
    __syncthreads();
    for (int i = threadIdx.y; i < 32; i += 8) {
        float w = t[threadIdx.x][i];                     // = W[k0+tx][nb+i]
        __half hi = __float2half_rn(w);
        __half lo = __float2half_rn(w - __half2float(hi));
        size_t base = (size_t)(nb + i) * KF + (k0 + threadIdx.x);
        WT[base] = hi;
        WT[base + 2048] = lo;
    }
}

// ---------------- FFMA split-K GEMM for inputs @ W0 (runs once, fp32 exact) ----------------
template <int N, int KTOT, int CHUNK, int BT, int T>
__global__ void __launch_bounds__(T) gemm_partial(const float* __restrict__ A,
                                                  const float* __restrict__ W,
                                                  float* __restrict__ P)
{
    __shared__ float As[BT][CHUNK];
    const int j0 = blockIdx.x * (T * 4) + threadIdx.x * 4;
    const int b0 = blockIdx.y * BT;
    const int k0 = blockIdx.z * CHUNK;
    for (int x = threadIdx.x; x < BT * CHUNK; x += T) {
        int bb = x / CHUNK, ii = x - bb * CHUNK;
        As[bb][ii] = A[(size_t)(b0 + bb) * KTOT + k0 + ii];
    }
    __syncthreads();
    float4 acc[BT];
#pragma unroll
    for (int b = 0; b < BT; b++) acc[b] = make_float4(0.f, 0.f, 0.f, 0.f);
    const float* Wp = W + (size_t)k0 * N + j0;
#pragma unroll 2
    for (int i = 0; i < CHUNK; i++) {
        float4 w = *(const float4*)(Wp + (size_t)i * N);
#pragma unroll
        for (int b = 0; b < BT; b++) {
            float a = As[b][i];
            acc[b].x += a * w.x; acc[b].y += a * w.y;
            acc[b].z += a * w.z; acc[b].w += a * w.w;
        }
    }
#pragma unroll
    for (int b = 0; b < BT; b++)
        *(float4*)(P + ((size_t)blockIdx.z * BATCH + b0 + b) * N + j0) = acc[b];
}

// ---------------- elementwise helpers ----------------
__device__ __forceinline__ void f4_add(float4& a, const float4 b) {
    a.x += b.x; a.y += b.y; a.z += b.z; a.w += b.w;
}
__device__ __forceinline__ float4 f4_axpy(float al, const float4 a, const float4 b) {
    return make_float4(fmaf(al, a.x, b.x), fmaf(al, a.y, b.y), fmaf(al, a.z, b.z), fmaf(al, a.w, b.w));
}
__device__ __forceinline__ void lif_spike_reset(float4& m, float4& spk) {
    bool fx = (m.x - 1.0f) > 0.0f, fy = (m.y - 1.0f) > 0.0f;
    bool fz = (m.z - 1.0f) > 0.0f, fw = (m.w - 1.0f) > 0.0f;
    spk.x = fx ? 1.0f : 0.0f; if (fx) m.x = 0.0f;
    spk.y = fy ? 1.0f : 0.0f; if (fy) m.y = 0.0f;
    spk.z = fz ? 1.0f : 0.0f; if (fz) m.z = 0.0f;
    spk.w = fw ? 1.0f : 0.0f; if (fw) m.w = 0.0f;
}
// write 4 spikes (idx = float4 index over [128][2048]) to duplicated fp16 buffer
__device__ __forceinline__ void store_spk_h(__half* base, int idx, const float4 spk) {
    __half2* sp = (__half2*)base;
    int m = idx >> 9, j = idx & 511;
    size_t o = (size_t)m * 2048 + j * 2;   // row = 4096 halves = 2048 half2
    __half2 lohalf = __floats2half2_rn(spk.x, spk.y);
    __half2 hihalf = __floats2half2_rn(spk.z, spk.w);
    sp[o] = lohalf;        sp[o + 1] = hihalf;
    sp[o + 1024] = lohalf; sp[o + 1025] = hihalf;   // +2048 halves (duplicate)
}

__global__ void init_states()
{
    int idx = blockIdx.x * blockDim.x + threadIdx.x;   // < 65536
    float4 z = make_float4(0.f, 0.f, 0.f, 0.f);
    ((float4*)g_s1)[idx] = z;
    ((float4*)g_m1)[idx] = z;
    if (idx < BATCH * N2 / 4) { ((float4*)g_s2)[idx] = z; ((float4*)g_m2)[idx] = z; }
}

__global__ void reduce0()
{
    int idx = blockIdx.x * blockDim.x + threadIdx.x;   // < 65536
    float4 h = make_float4(0.f, 0.f, 0.f, 0.f);
#pragma unroll
    for (int ks = 0; ks < 8; ks++) f4_add(h, ((const float4*)g_p1)[(size_t)ks * 65536 + idx]);
    ((float4*)g_H0)[idx] = h;
    float4 m = h, spk;
    lif_spike_reset(m, spk);
    ((float4*)g_m0)[idx] = m;
    store_spk_h(g_spk0h, idx, spk);
}

__global__ void lif1()
{
    int idx = blockIdx.x * blockDim.x + threadIdx.x;   // < 65536
    float4 h = make_float4(0.f, 0.f, 0.f, 0.f);
#pragma unroll
    for (int ks = 0; ks < 8; ks++) f4_add(h, ((const float4*)g_p1)[(size_t)ks * 65536 + idx]);
    float4 s = f4_axpy(ALPHA_C, ((float4*)g_s1)[idx], h);
    float4 m = f4_axpy(BETA_C, ((float4*)g_m1)[idx], s);
    float4 spk;
    lif_spike_reset(m, spk);
    ((float4*)g_s1)[idx] = s;
    ((float4*)g_m1)[idx] = m;
    store_spk_h(g_spk1h, idx, spk);
}

__global__ void lif2_l0()
{
    int gid = blockIdx.x * blockDim.x + threadIdx.x;
    if (gid < 16384) {                                  // layer2: 128x512/4
        float4 h = make_float4(0.f, 0.f, 0.f, 0.f);
#pragma unroll
        for (int ks = 0; ks < 16; ks++) f4_add(h, ((const float4*)g_p2)[(size_t)ks * 16384 + gid]);
        float4 s = f4_axpy(ALPHA_C, ((float4*)g_s2)[gid], h);
        float4 m = f4_axpy(BETA_C, ((float4*)g_m2)[gid], s);   // no reset on output layer
        ((float4*)g_s2)[gid] = s;
        ((float4*)g_m2)[gid] = m;
    } else {                                            // layer0 for next step
        int idx = gid - 16384;                          // < 65536
        float4 m = f4_axpy(BETA_C, ((float4*)g_m0)[idx], ((float4*)g_H0)[idx]);
        float4 spk;
        lif_spike_reset(m, spk);
        ((float4*)g_m0)[idx] = m;
        store_spk_h(g_spk0h, idx, spk);
    }
}

__global__ void copy_out(float* __restrict__ out)
{
    int idx = blockIdx.x * blockDim.x + threadIdx.x;    // < 16384
    ((float4*)out)[idx] = ((const float4*)g_m2)[idx];
}

// ---------------- launch ----------------
extern "C" void kernel_launch(void* const* d_in, const int* in_sizes, int n_in,
                              void* d_out, int out_size)
{
    const float* inp = nullptr; const float* W0 = nullptr;
    const float* W1 = nullptr;  const float* W2 = nullptr;
    for (int i = 0; i < n_in; i++) {
        switch (in_sizes[i]) {
            case BATCH * K0: inp = (const float*)d_in[i]; break;
            case K0 * N0:    W0  = (const float*)d_in[i]; break;
            case 2048 * N1:  W1  = (const float*)d_in[i]; break;
            case 2048 * N2:  W2  = (const float*)d_in[i]; break;
        }
    }

    float *p1, *p2;
    __half *spk0, *spk1, *w1t, *w2t;
    cudaGetSymbolAddress((void**)&p1,   g_p1);
    cudaGetSymbolAddress((void**)&p2,   g_p2);
    cudaGetSymbolAddress((void**)&spk0, g_spk0h);
    cudaGetSymbolAddress((void**)&spk1, g_spk1h);
    cudaGetSymbolAddress((void**)&w1t,  g_W1Th);
    cudaGetSymbolAddress((void**)&w2t,  g_W2Th);

    init_states<<<256, 256>>>();
    conv_transpose<<<dim3(64, 64), dim3(32, 8)>>>(W1, w1t);
    conv_transpose<<<dim3(64, 16), dim3(32, 8)>>>(W2, w2t);

    // H0 = inputs @ W0 (once, fp32)
    gemm_partial<N0, K0, 128, 16, 256><<<dim3(2, 8, 8), 256>>>(inp, W0, p1);
    reduce0<<<256, 256>>>();

    for (int t = 0; t < TSTEPS; t++) {
        gemm_mma<512, 2048><<<dim3(16, 8), 256>>>(spk0, w1t, p1);   // h1 partials (8 splits)
        lif1<<<256, 256>>>();                                       // -> spk1
        gemm_mma<256, 512><<<dim3(4, 16), 256>>>(spk1, w2t, p2);    // h2 partials (16 splits)
        lif2_l0<<<320, 256>>>();                                    // l2 update + l0 next
    }

    copy_out<<<64, 256>>>((float*)d_out);
}

// round 4
// speedup vs baseline: 2.5943x; 1.1001x over previous
#include <cuda_runtime.h>
#include <cuda_fp16.h>
#include <cstdint>

#define BATCH 128
#define N0 2048
#define N1 2048
#define N2 512
#define K0 1024
#define KF 4096            // hi|lo concatenated K dimension
#define ALPHA_C 0.9f
#define BETA_C  0.85f
#define TSTEPS 50
#define NCTA 128
#define RS 40              // smem row stride in halves -> conflict-free ldmatrix

// ---------------- static device scratch ----------------
__device__ float g_H0[BATCH * N0];
__device__ float g_m0[BATCH * N0];
__device__ float g_s1[BATCH * N1];
__device__ float g_m1[BATCH * N1];
__device__ float g_s2[BATCH * N2];
__device__ float g_m2[BATCH * N2];
__device__ __half g_spk0h[BATCH * KF];     // layer0 spikes fp16, duplicated halves
__device__ __half g_spk1h[BATCH * KF];     // layer1 spikes fp16, duplicated halves
__device__ __half g_inh[BATCH * KF];       // input ext: [hi | lo | hi | 0]
__device__ __half g_W0Th[N0 * KF];         // [n][k]: [hiW | hiW | loW | 0]
__device__ __half g_W1Th[N1 * KF];         // [n][k]: k<2048 hi, k>=2048 lo
__device__ __half g_W2Th[N2 * KF];
__device__ float g_p1[8 * BATCH * N1];     // split-K partials (H0 GEMM / GEMM1)
__device__ float g_p2[32 * BATCH * N2];    // split-K partials GEMM2
__device__ unsigned g_flags[NCTA];         // grid barrier flags

// ---------------- PTX helpers ----------------
__device__ __forceinline__ uint32_t smem_u32(const void* p) {
    uint32_t a;
    asm("{ .reg .u64 t; cvta.to.shared.u64 t, %1; cvt.u32.u64 %0, t; }" : "=r"(a) : "l"(p));
    return a;
}
__device__ __forceinline__ void cp16(uint32_t dst, const void* src) {
    asm volatile("cp.async.cg.shared.global [%0], [%1], 16;" :: "r"(dst), "l"(src));
}
__device__ __forceinline__ void ldmx4(uint32_t addr, uint32_t& r0, uint32_t& r1,
                                      uint32_t& r2, uint32_t& r3) {
    asm volatile("ldmatrix.sync.aligned.m8n8.x4.shared.b16 {%0,%1,%2,%3}, [%4];"
                 : "=r"(r0), "=r"(r1), "=r"(r2), "=r"(r3) : "r"(addr));
}
__device__ __forceinline__ void mma16816(float* d, const uint32_t* a, const uint32_t* b) {
    asm volatile(
        "mma.sync.aligned.m16n8k16.row.col.f32.f16.f16.f32 "
        "{%0,%1,%2,%3}, {%4,%5,%6,%7}, {%8,%9}, {%0,%1,%2,%3};"
        : "+f"(d[0]), "+f"(d[1]), "+f"(d[2]), "+f"(d[3])
        : "r"(a[0]), "r"(a[1]), "r"(a[2]), "r"(a[3]), "r"(b[0]), "r"(b[1]));
}

// ---------------- grid-wide barrier (all CTAs resident; flag-based) ----------------
__device__ __forceinline__ void gridbar(unsigned gen) {
    __syncthreads();
    __threadfence();
    if (threadIdx.x == 0) atomicExch(&g_flags[blockIdx.x], gen);
    if (threadIdx.x < NCTA) {
        while (atomicAdd(&g_flags[threadIdx.x], 0u) < gen) { }
    }
    __threadfence();
    __syncthreads();
}

// ---------------- HMMA GEMM body (128x128 tile, K-slice KLOC) ----------------
// Pp = P + ks*BATCH*NFULL (partial base).  A [128][KF], B [NFULL][KF] k-major fp16.
template <int KLOC, int NFULL>
__device__ __forceinline__ void gemm_body(const __half* __restrict__ A,
                                          const __half* __restrict__ B,
                                          float* __restrict__ Pp,
                                          int n0, int kbase,
                                          __half* sAb, __half* sBb)
{
    constexpr int S = KLOC / 32;
    const int tid = threadIdx.x, lane = tid & 31, wid = tid >> 5;
    const int wm = wid & 3, wn = wid >> 2;

    float acc[2][8][4];
    #pragma unroll
    for (int mt = 0; mt < 2; mt++)
        #pragma unroll
        for (int nt = 0; nt < 8; nt++)
            #pragma unroll
            for (int q = 0; q < 4; q++) acc[mt][nt][q] = 0.f;

    auto load_stage = [&](int s) {
        const int buf = s & 1;
        const int k0 = kbase + s * 32;
        __half* dA = sAb + buf * (128 * RS);
        __half* dB = sBb + buf * (128 * RS);
        #pragma unroll
        for (int c = tid; c < 512; c += 256) {
            int r = c >> 2, sub = c & 3;
            cp16(smem_u32(dA + r * RS + sub * 8), A + (size_t)r * KF + k0 + sub * 8);
        }
        #pragma unroll
        for (int c = tid; c < 512; c += 256) {
            int r = c >> 2, sub = c & 3;
            cp16(smem_u32(dB + r * RS + sub * 8), B + (size_t)(n0 + r) * KF + k0 + sub * 8);
        }
        asm volatile("cp.async.commit_group;" ::: "memory");
    };

    load_stage(0);

    for (int s = 0; s < S; s++) {
        if (s + 1 < S) {
            load_stage(s + 1);
            asm volatile("cp.async.wait_group 1;" ::: "memory");
        } else {
            asm volatile("cp.async.wait_group 0;" ::: "memory");
        }
        __syncthreads();
        const __half* bufA = sAb + (s & 1) * (128 * RS);
        const __half* bufB = sBb + (s & 1) * (128 * RS);
        #pragma unroll
        for (int ks = 0; ks < 2; ks++) {
            uint32_t a[2][4], b[8][2];
            #pragma unroll
            for (int mt = 0; mt < 2; mt++) {
                int row = wm * 32 + mt * 16 + (lane & 15);
                uint32_t ad = smem_u32(bufA + row * RS + ks * 16 + (lane >> 4) * 8);
                ldmx4(ad, a[mt][0], a[mt][1], a[mt][2], a[mt][3]);
            }
            #pragma unroll
            for (int q = 0; q < 4; q++) {
                int nr = wn * 64 + q * 16 + (lane >> 4) * 8 + (lane & 7);
                uint32_t bd = smem_u32(bufB + nr * RS + ks * 16 + ((lane >> 3) & 1) * 8);
                ldmx4(bd, b[2 * q][0], b[2 * q][1], b[2 * q + 1][0], b[2 * q + 1][1]);
            }
            #pragma unroll
            for (int mt = 0; mt < 2; mt++)
                #pragma unroll
                for (int nt = 0; nt < 8; nt++)
                    mma16816(acc[mt][nt], a[mt], b[nt]);
        }
        __syncthreads();
    }

    float* Pb = Pp + n0;
    #pragma unroll
    for (int mt = 0; mt < 2; mt++) {
        int r = wm * 32 + mt * 16 + (lane >> 2);
        #pragma unroll
        for (int nt = 0; nt < 8; nt++) {
            int cc = wn * 64 + nt * 8 + (lane & 3) * 2;
            *(float2*)(Pb + (size_t)r * NFULL + cc)       = make_float2(acc[mt][nt][0], acc[mt][nt][1]);
            *(float2*)(Pb + (size_t)(r + 8) * NFULL + cc) = make_float2(acc[mt][nt][2], acc[mt][nt][3]);
        }
    }
}

// ---------------- standalone GEMM kernel (used once for H0) ----------------
template <int KLOC, int NFULL>
__global__ void __launch_bounds__(256) gemm_mma(const __half* __restrict__ A,
                                                const __half* __restrict__ B,
                                                float* __restrict__ P)
{
    __shared__ __align__(128) __half sA[2 * 128 * RS];
    __shared__ __align__(128) __half sB[2 * 128 * RS];
    gemm_body<KLOC, NFULL>(A, B, P + (size_t)blockIdx.y * BATCH * NFULL,
                           blockIdx.x * 128, blockIdx.y * KLOC, sA, sB);
}

// ---------------- elementwise helpers ----------------
__device__ __forceinline__ void f4_add(float4& a, const float4 b) {
    a.x += b.x; a.y += b.y; a.z += b.z; a.w += b.w;
}
__device__ __forceinline__ float4 f4_axpy(float al, const float4 a, const float4 b) {
    return make_float4(fmaf(al, a.x, b.x), fmaf(al, a.y, b.y), fmaf(al, a.z, b.z), fmaf(al, a.w, b.w));
}
__device__ __forceinline__ void lif_spike_reset(float4& m, float4& spk) {
    bool fx = (m.x - 1.0f) > 0.0f, fy = (m.y - 1.0f) > 0.0f;
    bool fz = (m.z - 1.0f) > 0.0f, fw = (m.w - 1.0f) > 0.0f;
    spk.x = fx ? 1.0f : 0.0f; if (fx) m.x = 0.0f;
    spk.y = fy ? 1.0f : 0.0f; if (fy) m.y = 0.0f;
    spk.z = fz ? 1.0f : 0.0f; if (fz) m.z = 0.0f;
    spk.w = fw ? 1.0f : 0.0f; if (fw) m.w = 0.0f;
}
__device__ __forceinline__ void store_spk_h(__half* base, int idx, const float4 spk) {
    __half2* sp = (__half2*)base;
    int m = idx >> 9, j = idx & 511;
    size_t o = (size_t)m * 2048 + j * 2;
    __half2 p0 = __floats2half2_rn(spk.x, spk.y);
    __half2 p1 = __floats2half2_rn(spk.z, spk.w);
    sp[o] = p0;        sp[o + 1] = p1;
    sp[o + 1024] = p0; sp[o + 1025] = p1;   // duplicate K half
}

// ---------------- persistent loop kernel ----------------
__global__ void __launch_bounds__(256, 1) persistent_loop(float* __restrict__ out)
{
    __shared__ __align__(128) __half sA[2 * 128 * RS];
    __shared__ __align__(128) __half sB[2 * 128 * RS];
    const int cta = blockIdx.x;
    const int tid = threadIdx.x;
    unsigned gen = 0;

    for (int t = 0; t < TSTEPS; t++) {
        // ---- phase A: lif2(t-1) + GEMM1 ----
        if (t > 0 && tid < 128) {
            int idx = cta * 128 + tid;                       // f4 over [128][512]
            float4 h = make_float4(0.f, 0.f, 0.f, 0.f);
            #pragma unroll
            for (int ks = 0; ks < 32; ks++) f4_add(h, ((const float4*)g_p2)[(size_t)ks * 16384 + idx]);
            float4 s = f4_axpy(ALPHA_C, ((float4*)g_s2)[idx], h);
            float4 m = f4_axpy(BETA_C, ((float4*)g_m2)[idx], s);   // output layer: no reset
            ((float4*)g_s2)[idx] = s;
            ((float4*)g_m2)[idx] = m;
        }
        gemm_body<512, 2048>(g_spk0h, g_W1Th,
                             g_p1 + (size_t)(cta >> 4) * BATCH * 2048,
                             (cta & 15) * 128, (cta >> 4) * 512, sA, sB);
        gridbar(++gen);

        // ---- phase B: lif1 -> spk1 ; layer0 next-step -> spk0 ----
        #pragma unroll
        for (int r = 0; r < 2; r++) {
            int idx = cta * 512 + r * 256 + tid;             // f4 over [128][2048]
            float4 h = make_float4(0.f, 0.f, 0.f, 0.f);
            #pragma unroll
            for (int ks = 0; ks < 8; ks++) f4_add(h, ((const float4*)g_p1)[(size_t)ks * 65536 + idx]);
            float4 s = f4_axpy(ALPHA_C, ((float4*)g_s1)[idx], h);
            float4 m = f4_axpy(BETA_C, ((float4*)g_m1)[idx], s);
            float4 spk;
            lif_spike_reset(m, spk);
            ((float4*)g_s1)[idx] = s;
            ((float4*)g_m1)[idx] = m;
            store_spk_h(g_spk1h, idx, spk);
        }
        if (t + 1 < TSTEPS) {
            #pragma unroll
            for (int r = 0; r < 2; r++) {
                int idx = cta * 512 + r * 256 + tid;
                float4 m = f4_axpy(BETA_C, ((float4*)g_m0)[idx], ((float4*)g_H0)[idx]);
                float4 spk;
                lif_spike_reset(m, spk);
                ((float4*)g_m0)[idx] = m;
                store_spk_h(g_spk0h, idx, spk);
            }
        }
        gridbar(++gen);

        // ---- phase C: GEMM2 (32 K-splits, KLOC=128) ----
        gemm_body<128, 512>(g_spk1h, g_W2Th,
                            g_p2 + (size_t)(cta >> 2) * BATCH * 512,
                            (cta & 3) * 128, (cta >> 2) * 128, sA, sB);
        gridbar(++gen);
    }

    // ---- final lif2 + output ----
    if (tid < 128) {
        int idx = cta * 128 + tid;
        float4 h = make_float4(0.f, 0.f, 0.f, 0.f);
        #pragma unroll
        for (int ks = 0; ks < 32; ks++) f4_add(h, ((const float4*)g_p2)[(size_t)ks * 16384 + idx]);
        float4 s = f4_axpy(ALPHA_C, ((float4*)g_s2)[idx], h);
        float4 m = f4_axpy(BETA_C, ((float4*)g_m2)[idx], s);
        ((float4*)out)[idx] = m;
    }
}

// ---------------- one-time prep kernels ----------------
// W [K,N] f32 -> WT [N][KF]: hi at k, lo at k+2048 (coalesced half2 writes)
__global__ void conv_w(const float* __restrict__ W, __half* __restrict__ WT, int N)
{
    __shared__ float t[32][33];
    const int k0 = blockIdx.x * 32, nb = blockIdx.y * 32;
    const int tx = threadIdx.x, ty = threadIdx.y;
    for (int i = ty; i < 32; i += 8)
        t[i][tx] = W[(size_t)(k0 + i) * N + nb + tx];
    __syncthreads();
    if (tx < 16) {
        for (int n2 = ty; n2 < 32; n2 += 8) {
            float w0 = t[2 * tx][n2], w1 = t[2 * tx + 1][n2];
            __half h0 = __float2half_rn(w0), h1 = __float2half_rn(w1);
            __half l0 = __float2half_rn(w0 - __half2float(h0));
            __half l1 = __float2half_rn(w1 - __half2float(h1));
            size_t row = (size_t)(nb + n2) * KF;
            ((__half2*)(WT + row + k0))[tx]        = __halves2half2(h0, h1);
            ((__half2*)(WT + row + 2048 + k0))[tx] = __halves2half2(l0, l1);
        }
    }
}

// W0 [1024,2048] f32 -> W0T_ext [2048][4096]: [hi | hi | lo | 0]
__global__ void conv_w0(const float* __restrict__ W, __half* __restrict__ WT)
{
    __shared__ float t[32][33];
    const int k0 = blockIdx.x * 32, nb = blockIdx.y * 32;
    const int tx = threadIdx.x, ty = threadIdx.y;
    for (int i = ty; i < 32; i += 8)
        t[i][tx] = W[(size_t)(k0 + i) * 2048 + nb + tx];
    __syncthreads();
    if (tx < 16) {
        for (int n2 = ty; n2 < 32; n2 += 8) {
            float w0 = t[2 * tx][n2], w1 = t[2 * tx + 1][n2];
            __half h0 = __float2half_rn(w0), h1 = __float2half_rn(w1);
            __half l0 = __float2half_rn(w0 - __half2float(h0));
            __half l1 = __float2half_rn(w1 - __half2float(h1));
            size_t row = (size_t)(nb + n2) * KF;
            __half2 hh = __halves2half2(h0, h1);
            ((__half2*)(WT + row + k0))[tx]        = hh;                        // seg0: hi
            ((__half2*)(WT + row + 1024 + k0))[tx] = hh;                        // seg1: hi
            ((__half2*)(WT + row + 2048 + k0))[tx] = __halves2half2(l0, l1);    // seg2: lo
            ((__half2*)(WT + row + 3072 + k0))[tx] = __halves2half2(__float2half_rn(0.f), __float2half_rn(0.f));
        }
    }
}

// inputs [128,1024] f32 -> g_inh [128][4096]: [hi | lo | hi | 0]
__global__ void split_input(const float* __restrict__ inp)
{
    int g = blockIdx.x * blockDim.x + threadIdx.x;     // < 131072
    int m = g >> 10, k = g & 1023;
    float v = inp[g];
    __half hi = __float2half_rn(v);
    __half lo = __float2half_rn(v - __half2float(hi));
    size_t row = (size_t)m * KF;
    g_inh[row + k] = hi;
    g_inh[row + 1024 + k] = lo;
    g_inh[row + 2048 + k] = hi;
    g_inh[row + 3072 + k] = __float2half_rn(0.f);
}

// reduce 8 H0 partials -> H0, then step-0 layer0 update -> spk0
__global__ void reduce0()
{
    int idx = blockIdx.x * blockDim.x + threadIdx.x;   // < 65536
    float4 h = make_float4(0.f, 0.f, 0.f, 0.f);
#pragma unroll
    for (int ks = 0; ks < 8; ks++) f4_add(h, ((const float4*)g_p1)[(size_t)ks * 65536 + idx]);
    ((float4*)g_H0)[idx] = h;
    float4 m = h, spk;
    lif_spike_reset(m, spk);
    ((float4*)g_m0)[idx] = m;
    store_spk_h(g_spk0h, idx, spk);
}

__global__ void init_states()
{
    int idx = blockIdx.x * blockDim.x + threadIdx.x;   // < 65536
    float4 z = make_float4(0.f, 0.f, 0.f, 0.f);
    ((float4*)g_s1)[idx] = z;
    ((float4*)g_m1)[idx] = z;
    if (idx < BATCH * N2 / 4) { ((float4*)g_s2)[idx] = z; ((float4*)g_m2)[idx] = z; }
    if (idx < NCTA) g_flags[idx] = 0u;
}

// ---------------- launch ----------------
extern "C" void kernel_launch(void* const* d_in, const int* in_sizes, int n_in,
                              void* d_out, int out_size)
{
    const float* inp = nullptr; const float* W0 = nullptr;
    const float* W1 = nullptr;  const float* W2 = nullptr;
    for (int i = 0; i < n_in; i++) {
        switch (in_sizes[i]) {
            case BATCH * K0: inp = (const float*)d_in[i]; break;
            case K0 * N0:    W0  = (const float*)d_in[i]; break;
            case 2048 * N1:  W1  = (const float*)d_in[i]; break;
            case 2048 * N2:  W2  = (const float*)d_in[i]; break;
        }
    }

    float* p1;
    __half *inh, *w0t, *w1t, *w2t;
    cudaGetSymbolAddress((void**)&p1,  g_p1);
    cudaGetSymbolAddress((void**)&inh, g_inh);
    cudaGetSymbolAddress((void**)&w0t, g_W0Th);
    cudaGetSymbolAddress((void**)&w1t, g_W1Th);
    cudaGetSymbolAddress((void**)&w2t, g_W2Th);

    init_states<<<256, 256>>>();
    conv_w0<<<dim3(32, 64), dim3(32, 8)>>>(W0, w0t);
    conv_w<<<dim3(64, 64), dim3(32, 8)>>>(W1, w1t, N1);
    conv_w<<<dim3(64, 16), dim3(32, 8)>>>(W2, w2t, N2);
    split_input<<<512, 256>>>(inp);

    // H0 = inputs @ W0 via HMMA (8 K-splits), then reduce + step-0 layer0
    gemm_mma<512, 2048><<<dim3(16, 8), 256>>>(inh, w0t, p1);
    reduce0<<<256, 256>>>();

    // all 50 timesteps in one persistent kernel
    persistent_loop<<<NCTA, 256>>>((float*)d_out);
}

// round 6
// speedup vs baseline: 2.7654x; 1.0659x over previous
#include <cuda_runtime.h>
#include <cuda_fp16.h>
#include <cstdint>

#define BATCH 128
#define N0 2048
#define N1 2048
#define N2 512
#define K0 1024
#define KF 4096            // hi|lo concatenated K dimension
#define ALPHA_C 0.9f
#define BETA_C  0.85f
#define TSTEPS 50
#define NCTA 128
#define RS 40              // smem row stride in halves -> conflict-free ldmatrix
#define STAGE_H (128 * RS) // halves per stage buffer per operand
#define SMEM_BYTES (3 * STAGE_H * 2 * 2 * 2 / 2)  // 3 stages * (A+B) * STAGE_H halves * 2B = 61440

// ---------------- static device scratch ----------------
__device__ float g_H0[BATCH * N0];
__device__ float g_m0[BATCH * N0];
__device__ float g_s1[BATCH * N1];
__device__ float g_m1[BATCH * N1];
__device__ float g_s2[BATCH * N2];
__device__ float g_m2[BATCH * N2];
__device__ __half g_spk0h[BATCH * KF];     // layer0 spikes fp16, duplicated halves
__device__ __half g_spk1h[BATCH * KF];     // layer1 spikes fp16, duplicated halves
__device__ __half g_inh[BATCH * KF];       // input ext: [hi | lo | hi | 0]
__device__ __half g_W0Th[N0 * KF];         // [n][k]: [hiW | hiW | loW | 0]
__device__ __half g_W1Th[N1 * KF];         // [n][k]: k<2048 hi, k>=2048 lo
__device__ __half g_W2Th[N2 * KF];
__device__ float g_p1[8 * BATCH * N1];     // split-K partials (H0 GEMM / GEMM1)
__device__ float g_p2[32 * BATCH * N2];    // split-K partials GEMM2
__device__ unsigned g_ctr;                 // grid barrier counter

// ---------------- PTX helpers ----------------
__device__ __forceinline__ uint32_t smem_u32(const void* p) {
    uint32_t a;
    asm("{ .reg .u64 t; cvta.to.shared.u64 t, %1; cvt.u32.u64 %0, t; }" : "=r"(a) : "l"(p));
    return a;
}
__device__ __forceinline__ void cp16(uint32_t dst, const void* src) {
    asm volatile("cp.async.cg.shared.global [%0], [%1], 16;" :: "r"(dst), "l"(src));
}
__device__ __forceinline__ void ldmx4(uint32_t addr, uint32_t& r0, uint32_t& r1,
                                      uint32_t& r2, uint32_t& r3) {
    asm volatile("ldmatrix.sync.aligned.m8n8.x4.shared.b16 {%0,%1,%2,%3}, [%4];"
                 : "=r"(r0), "=r"(r1), "=r"(r2), "=r"(r3) : "r"(addr));
}
__device__ __forceinline__ void mma16816(float* d, const uint32_t* a, const uint32_t* b) {
    asm volatile(
        "mma.sync.aligned.m16n8k16.row.col.f32.f16.f16.f32 "
        "{%0,%1,%2,%3}, {%4,%5,%6,%7}, {%8,%9}, {%0,%1,%2,%3};"
        : "+f"(d[0]), "+f"(d[1]), "+f"(d[2]), "+f"(d[3])
        : "r"(a[0]), "r"(a[1]), "r"(a[2]), "r"(a[3]), "r"(b[0]), "r"(b[1]));
}
__device__ __forceinline__ unsigned ld_acq(const unsigned* p) {
    unsigned v;
    asm volatile("ld.global.acquire.gpu.u32 %0, [%1];" : "=r"(v) : "l"(p) : "memory");
    return v;
}
__device__ __forceinline__ void red_rel_add(unsigned* p, unsigned v) {
    asm volatile("red.release.gpu.global.add.u32 [%0], %1;" :: "l"(p), "r"(v) : "memory");
}

// ---------------- grid-wide barrier (single counter, load-polling) ----------------
__device__ __forceinline__ void gridbar(unsigned target) {
    __syncthreads();
    if (threadIdx.x == 0) {
        red_rel_add(&g_ctr, 1u);
        while (ld_acq(&g_ctr) < target) { }
    }
    __syncthreads();
}

// ---------------- HMMA GEMM body: 128x128 tile, K-slice KLOC, 3-stage pipeline ----------------
// A [128][KF], B [NFULL][KF] k-major fp16.  Pp points at this split's partial base.
template <int KLOC, int NFULL>
__device__ __forceinline__ void gemm_body(const __half* __restrict__ A,
                                          const __half* __restrict__ B,
                                          float* __restrict__ Pp,
                                          int n0, int kbase,
                                          __half* sAb, __half* sBb)
{
    constexpr int S = KLOC / 32;
    const int tid = threadIdx.x, lane = tid & 31, wid = tid >> 5;
    const int wm = wid & 3, wn = wid >> 2;

    float acc[2][8][4];
    #pragma unroll
    for (int mt = 0; mt < 2; mt++)
        #pragma unroll
        for (int nt = 0; nt < 8; nt++)
            #pragma unroll
            for (int q = 0; q < 4; q++) acc[mt][nt][q] = 0.f;

    auto load_stage = [&](int s) {
        const int buf = s % 3;
        const int k0 = kbase + s * 32;
        __half* dA = sAb + buf * STAGE_H;
        __half* dB = sBb + buf * STAGE_H;
        {
            int r = tid >> 1, sub = (tid & 1) * 2;            // 2 cp16 per thread (A)
            cp16(smem_u32(dA + r * RS + sub * 8),     A + (size_t)r * KF + k0 + sub * 8);
            cp16(smem_u32(dA + r * RS + sub * 8 + 8), A + (size_t)r * KF + k0 + sub * 8 + 8);
            cp16(smem_u32(dB + r * RS + sub * 8),     B + (size_t)(n0 + r) * KF + k0 + sub * 8);
            cp16(smem_u32(dB + r * RS + sub * 8 + 8), B + (size_t)(n0 + r) * KF + k0 + sub * 8 + 8);
        }
        asm volatile("cp.async.commit_group;" ::: "memory");
    };

    load_stage(0);
    load_stage(1);

    for (int s = 0; s < S; s++) {
        if (s + 1 < S) { asm volatile("cp.async.wait_group 1;" ::: "memory"); }
        else           { asm volatile("cp.async.wait_group 0;" ::: "memory"); }
        __syncthreads();
        if (s + 2 < S) load_stage(s + 2);

        const __half* bufA = sAb + (s % 3) * STAGE_H;
        const __half* bufB = sBb + (s % 3) * STAGE_H;
        #pragma unroll
        for (int ks = 0; ks < 2; ks++) {
            uint32_t a[2][4], b[8][2];
            #pragma unroll
            for (int mt = 0; mt < 2; mt++) {
                int row = wm * 32 + mt * 16 + (lane & 15);
                uint32_t ad = smem_u32(bufA + row * RS + ks * 16 + (lane >> 4) * 8);
                ldmx4(ad, a[mt][0], a[mt][1], a[mt][2], a[mt][3]);
            }
            #pragma unroll
            for (int q = 0; q < 4; q++) {
                int nr = wn * 64 + q * 16 + (lane >> 4) * 8 + (lane & 7);
                uint32_t bd = smem_u32(bufB + nr * RS + ks * 16 + ((lane >> 3) & 1) * 8);
                ldmx4(bd, b[2 * q][0], b[2 * q][1], b[2 * q + 1][0], b[2 * q + 1][1]);
            }
            #pragma unroll
            for (int mt = 0; mt < 2; mt++)
                #pragma unroll
                for (int nt = 0; nt < 8; nt++)
                    mma16816(acc[mt][nt], a[mt], b[nt]);
        }
    }

    float* Pb = Pp + n0;
    #pragma unroll
    for (int mt = 0; mt < 2; mt++) {
        int r = wm * 32 + mt * 16 + (lane >> 2);
        #pragma unroll
        for (int nt = 0; nt < 8; nt++) {
            int cc = wn * 64 + nt * 8 + (lane & 3) * 2;
            *(float2*)(Pb + (size_t)r * NFULL + cc)       = make_float2(acc[mt][nt][0], acc[mt][nt][1]);
            *(float2*)(Pb + (size_t)(r + 8) * NFULL + cc) = make_float2(acc[mt][nt][2], acc[mt][nt][3]);
        }
    }
}

// ---------------- standalone GEMM kernel (used once for H0) ----------------
template <int KLOC, int NFULL>
__global__ void __launch_bounds__(256) gemm_mma(const __half* __restrict__ A,
                                                const __half* __restrict__ B,
                                                float* __restrict__ P)
{
    extern __shared__ __align__(128) __half dynsm[];
    gemm_body<KLOC, NFULL>(A, B, P + (size_t)blockIdx.y * BATCH * NFULL,
                           blockIdx.x * 128, blockIdx.y * KLOC, dynsm, dynsm + 3 * STAGE_H);
}

// ---------------- elementwise helpers ----------------
__device__ __forceinline__ void f4_add(float4& a, const float4 b) {
    a.x += b.x; a.y += b.y; a.z += b.z; a.w += b.w;
}
__device__ __forceinline__ float4 f4_axpy(float al, const float4 a, const float4 b) {
    return make_float4(fmaf(al, a.x, b.x), fmaf(al, a.y, b.y), fmaf(al, a.z, b.z), fmaf(al, a.w, b.w));
}
__device__ __forceinline__ void lif_spike_reset(float4& m, float4& spk) {
    bool fx = (m.x - 1.0f) > 0.0f, fy = (m.y - 1.0f) > 0.0f;
    bool fz = (m.z - 1.0f) > 0.0f, fw = (m.w - 1.0f) > 0.0f;
    spk.x = fx ? 1.0f : 0.0f; if (fx) m.x = 0.0f;
    spk.y = fy ? 1.0f : 0.0f; if (fy) m.y = 0.0f;
    spk.z = fz ? 1.0f : 0.0f; if (fz) m.z = 0.0f;
    spk.w = fw ? 1.0f : 0.0f; if (fw) m.w = 0.0f;
}
__device__ __forceinline__ void store_spk_h(__half* base, int idx, const float4 spk) {
    __half2* sp = (__half2*)base;
    int m = idx >> 9, j = idx & 511;
    size_t o = (size_t)m * 2048 + j * 2;
    __half2 p0 = __floats2half2_rn(spk.x, spk.y);
    __half2 p1 = __floats2half2_rn(spk.z, spk.w);
    sp[o] = p0;        sp[o + 1] = p1;
    sp[o + 1024] = p0; sp[o + 1025] = p1;   // duplicate K half
}

// ---------------- persistent loop kernel ----------------
__global__ void __launch_bounds__(256, 1) persistent_loop(float* __restrict__ out)
{
    extern __shared__ __align__(128) __half dynsm[];
    __half* sA = dynsm;
    __half* sB = dynsm + 3 * STAGE_H;
    const int cta = blockIdx.x;
    const int tid = threadIdx.x;
    unsigned gen = 0;

    for (int t = 0; t < TSTEPS; t++) {
        // ---- phase A: lif2(t-1) + GEMM1 ----
        if (t > 0 && tid < 128) {
            int idx = cta * 128 + tid;                       // f4 over [128][512]
            float4 h = make_float4(0.f, 0.f, 0.f, 0.f);
            #pragma unroll
            for (int ks = 0; ks < 32; ks++) f4_add(h, ((const float4*)g_p2)[(size_t)ks * 16384 + idx]);
            float4 s = f4_axpy(ALPHA_C, ((float4*)g_s2)[idx], h);
            float4 m = f4_axpy(BETA_C, ((float4*)g_m2)[idx], s);   // output layer: no reset
            ((float4*)g_s2)[idx] = s;
            ((float4*)g_m2)[idx] = m;
        }
        gemm_body<512, 2048>(g_spk0h, g_W1Th,
                             g_p1 + (size_t)(cta >> 4) * BATCH * 2048,
                             (cta & 15) * 128, (cta >> 4) * 512, sA, sB);
        gridbar(++gen * NCTA);

        // ---- phase B: lif1 -> spk1 ; layer0 next-step -> spk0 ----
        #pragma unroll
        for (int r = 0; r < 2; r++) {
            int idx = cta * 512 + r * 256 + tid;             // f4 over [128][2048]
            float4 h = make_float4(0.f, 0.f, 0.f, 0.f);
            #pragma unroll
            for (int ks = 0; ks < 8; ks++) f4_add(h, ((const float4*)g_p1)[(size_t)ks * 65536 + idx]);
            float4 s = f4_axpy(ALPHA_C, ((float4*)g_s1)[idx], h);
            float4 m = f4_axpy(BETA_C, ((float4*)g_m1)[idx], s);
            float4 spk;
            lif_spike_reset(m, spk);
            ((float4*)g_s1)[idx] = s;
            ((float4*)g_m1)[idx] = m;
            store_spk_h(g_spk1h, idx, spk);
        }
        if (t + 1 < TSTEPS) {
            #pragma unroll
            for (int r = 0; r < 2; r++) {
                int idx = cta * 512 + r * 256 + tid;
                float4 m = f4_axpy(BETA_C, ((float4*)g_m0)[idx], ((float4*)g_H0)[idx]);
                float4 spk;
                lif_spike_reset(m, spk);
                ((float4*)g_m0)[idx] = m;
                store_spk_h(g_spk0h, idx, spk);
            }
        }
        gridbar(++gen * NCTA);

        // ---- phase C: GEMM2 (32 K-splits, KLOC=128) ----
        gemm_body<128, 512>(g_spk1h, g_W2Th,
                            g_p2 + (size_t)(cta >> 2) * BATCH * 512,
                            (cta & 3) * 128, (cta >> 2) * 128, sA, sB);
        gridbar(++gen * NCTA);
    }

    // ---- final lif2 + output ----
    if (tid < 128) {
        int idx = cta * 128 + tid;
        float4 h = make_float4(0.f, 0.f, 0.f, 0.f);
        #pragma unroll
        for (int ks = 0; ks < 32; ks++) f4_add(h, ((const float4*)g_p2)[(size_t)ks * 16384 + idx]);
        float4 s = f4_axpy(ALPHA_C, ((float4*)g_s2)[idx], h);
        float4 m = f4_axpy(BETA_C, ((float4*)g_m2)[idx], s);
        ((float4*)out)[idx] = m;
    }
}

// ---------------- one-time prep kernels ----------------
__global__ void conv_w(const float* __restrict__ W, __half* __restrict__ WT, int N)
{
    __shared__ float t[32][33];
    const int k0 = blockIdx.x * 32, nb = blockIdx.y * 32;
    const int tx = threadIdx.x, ty = threadIdx.y;
    for (int i = ty; i < 32; i += 8)
        t[i][tx] = W[(size_t)(k0 + i) * N + nb + tx];
    __syncthreads();
    if (tx < 16) {
        for (int n2 = ty; n2 < 32; n2 += 8) {
            float w0 = t[2 * tx][n2], w1 = t[2 * tx + 1][n2];
            __half h0 = __float2half_rn(w0), h1 = __float2half_rn(w1);
            __half l0 = __float2half_rn(w0 - __half2float(h0));
            __half l1 = __float2half_rn(w1 - __half2float(h1));
            size_t row = (size_t)(nb + n2) * KF;
            ((__half2*)(WT + row + k0))[tx]        = __halves2half2(h0, h1);
            ((__half2*)(WT + row + 2048 + k0))[tx] = __halves2half2(l0, l1);
        }
    }
}

__global__ void conv_w0(const float* __restrict__ W, __half* __restrict__ WT)
{
    __shared__ float t[32][33];
    const int k0 = blockIdx.x * 32, nb = blockIdx.y * 32;
    const int tx = threadIdx.x, ty = threadIdx.y;
    for (int i = ty; i < 32; i += 8)
        t[i][tx] = W[(size_t)(k0 + i) * 2048 + nb + tx];
    __syncthreads();
    if (tx < 16) {
        for (int n2 = ty; n2 < 32; n2 += 8) {
            float w0 = t[2 * tx][n2], w1 = t[2 * tx + 1][n2];
            __half h0 = __float2half_rn(w0), h1 = __float2half_rn(w1);
            __half l0 = __float2half_rn(w0 - __half2float(h0));
            __half l1 = __float2half_rn(w1 - __half2float(h1));
            size_t row = (size_t)(nb + n2) * KF;
            __half2 hh = __halves2half2(h0, h1);
            ((__half2*)(WT + row + k0))[tx]        = hh;                        // seg0: hi
            ((__half2*)(WT + row + 1024 + k0))[tx] = hh;                        // seg1: hi
            ((__half2*)(WT + row + 2048 + k0))[tx] = __halves2half2(l0, l1);    // seg2: lo
            ((__half2*)(WT + row + 3072 + k0))[tx] = __halves2half2(__float2half_rn(0.f), __float2half_rn(0.f));
        }
    }
}

__global__ void split_input(const float* __restrict__ inp)
{
    int g = blockIdx.x * blockDim.x + threadIdx.x;     // < 131072
    int m = g >> 10, k = g & 1023;
    float v = inp[g];
    __half hi = __float2half_rn(v);
    __half lo = __float2half_rn(v - __half2float(hi));
    size_t row = (size_t)m * KF;
    g_inh[row + k] = hi;
    g_inh[row + 1024 + k] = lo;
    g_inh[row + 2048 + k] = hi;
    g_inh[row + 3072 + k] = __float2half_rn(0.f);
}

__global__ void reduce0()
{
    int idx = blockIdx.x * blockDim.x + threadIdx.x;   // < 65536
    float4 h = make_float4(0.f, 0.f, 0.f, 0.f);
#pragma unroll
    for (int ks = 0; ks < 8; ks++) f4_add(h, ((const float4*)g_p1)[(size_t)ks * 65536 + idx]);
    ((float4*)g_H0)[idx] = h;
    float4 m = h, spk;
    lif_spike_reset(m, spk);
    ((float4*)g_m0)[idx] = m;
    store_spk_h(g_spk0h, idx, spk);
}

__global__ void init_states()
{
    int idx = blockIdx.x * blockDim.x + threadIdx.x;   // < 65536
    float4 z = make_float4(0.f, 0.f, 0.f, 0.f);
    ((float4*)g_s1)[idx] = z;
    ((float4*)g_m1)[idx] = z;
    if (idx < BATCH * N2 / 4) { ((float4*)g_s2)[idx] = z; ((float4*)g_m2)[idx] = z; }
    if (idx == 0) g_ctr = 0u;
}

// ---------------- launch ----------------
extern "C" void kernel_launch(void* const* d_in, const int* in_sizes, int n_in,
                              void* d_out, int out_size)
{
    const float* inp = nullptr; const float* W0 = nullptr;
    const float* W1 = nullptr;  const float* W2 = nullptr;
    for (int i = 0; i < n_in; i++) {
        switch (in_sizes[i]) {
            case BATCH * K0: inp = (const float*)d_in[i]; break;
            case K0 * N0:    W0  = (const float*)d_in[i]; break;
            case 2048 * N1:  W1  = (const float*)d_in[i]; break;
            case 2048 * N2:  W2  = (const float*)d_in[i]; break;
        }
    }

    float* p1;
    __half *inh, *w0t, *w1t, *w2t;
    cudaGetSymbolAddress((void**)&p1,  g_p1);
    cudaGetSymbolAddress((void**)&inh, g_inh);
    cudaGetSymbolAddress((void**)&w0t, g_W0Th);
    cudaGetSymbolAddress((void**)&w1t, g_W1Th);
    cudaGetSymbolAddress((void**)&w2t, g_W2Th);

    static bool attr_done = false;
    if (!attr_done) {
        cudaFuncSetAttribute(gemm_mma<512, 2048>, cudaFuncAttributeMaxDynamicSharedMemorySize, SMEM_BYTES);
        cudaFuncSetAttribute(persistent_loop, cudaFuncAttributeMaxDynamicSharedMemorySize, SMEM_BYTES);
        attr_done = true;
    }

    init_states<<<256, 256>>>();
    conv_w0<<<dim3(32, 64), dim3(32, 8)>>>(W0, w0t);
    conv_w<<<dim3(64, 64), dim3(32, 8)>>>(W1, w1t, N1);
    conv_w<<<dim3(64, 16), dim3(32, 8)>>>(W2, w2t, N2);
    split_input<<<512, 256>>>(inp);

    // H0 = inputs @ W0 via HMMA (8 K-splits), then reduce + step-0 layer0
    gemm_mma<512, 2048><<<dim3(16, 8), 256, SMEM_BYTES>>>(inh, w0t, p1);
    reduce0<<<256, 256>>>();

    // all 50 timesteps in one persistent kernel
    persistent_loop<<<NCTA, 256, SMEM_BYTES>>>((float*)d_out);
}

// round 8
// speedup vs baseline: 3.3109x; 1.1973x over previous
#include <cuda_runtime.h>
#include <cuda_fp16.h>
#include <cstdint>

#define BATCH 128
#define N0 2048
#define N1 2048
#define N2 512
#define K0 1024
#define KF 4096            // hi|lo concatenated K dimension
#define ALPHA_C 0.9f
#define BETA_C  0.85f
#define TSTEPS 50
#define NCTA 128

// ---- H0 standalone GEMM staging (old style) ----
#define RS 40
#define STAGE_H (128 * RS)
#define H0_SMEM_BYTES (3 * STAGE_H * 2 * 2)      // 61440

// ---- persistent kernel smem layout (halves) ----
#define W1_RS 520                                 // 512 + 8 pad
#define W2_RS 136                                 // 128 + 8 pad
#define A_RS  72                                  // 64 + 8 pad
#define A_STG (128 * A_RS)                        // 9216 halves / stage
#define SW1_OFF 0
#define SW2_OFF (128 * W1_RS)                     // 66560
#define SA_OFF  (SW2_OFF + 128 * W2_RS)           // 83968
#define PERS_SMEM_BYTES ((SA_OFF + 3 * A_STG) * 2)  // 223232 B

// ---------------- static device scratch ----------------
__device__ float g_H0[BATCH * N0];
__device__ float g_m0[BATCH * N0];
__device__ float g_s1[BATCH * N1];
__device__ float g_m1[BATCH * N1];
__device__ float g_s2[BATCH * N2];
__device__ float g_m2[BATCH * N2];
__device__ __half g_spk0h[BATCH * KF];     // layer0 spikes fp16, duplicated halves
__device__ __half g_spk1h[BATCH * KF];     // layer1 spikes fp16, duplicated halves
__device__ __half g_inh[BATCH * KF];       // input ext: [hi | lo | hi | 0]
__device__ __half g_W0Th[N0 * KF];         // [n][k]: [hiW | hiW | loW | 0]
__device__ __half g_W1Th[N1 * KF];         // [n][k]: k<2048 hi, k>=2048 lo
__device__ __half g_W2Th[N2 * KF];
__device__ float g_p1[8 * BATCH * N1];     // split-K partials (H0 GEMM / GEMM1)
__device__ float g_p2[32 * BATCH * N2];    // split-K partials GEMM2
__device__ unsigned g_ctr;                 // grid barrier counter

// ---------------- PTX helpers ----------------
__device__ __forceinline__ uint32_t smem_u32(const void* p) {
    uint32_t a;
    asm("{ .reg .u64 t; cvta.to.shared.u64 t, %1; cvt.u32.u64 %0, t; }" : "=r"(a) : "l"(p));
    return a;
}
__device__ __forceinline__ void cp16(uint32_t dst, const void* src) {
    asm volatile("cp.async.cg.shared.global [%0], [%1], 16;" :: "r"(dst), "l"(src));
}
__device__ __forceinline__ void ldmx4(uint32_t addr, uint32_t& r0, uint32_t& r1,
                                      uint32_t& r2, uint32_t& r3) {
    asm volatile("ldmatrix.sync.aligned.m8n8.x4.shared.b16 {%0,%1,%2,%3}, [%4];"
                 : "=r"(r0), "=r"(r1), "=r"(r2), "=r"(r3) : "r"(addr));
}
__device__ __forceinline__ void mma16816(float* d, const uint32_t* a, const uint32_t* b) {
    asm volatile(
        "mma.sync.aligned.m16n8k16.row.col.f32.f16.f16.f32 "
        "{%0,%1,%2,%3}, {%4,%5,%6,%7}, {%8,%9}, {%0,%1,%2,%3};"
        : "+f"(d[0]), "+f"(d[1]), "+f"(d[2]), "+f"(d[3])
        : "r"(a[0]), "r"(a[1]), "r"(a[2]), "r"(a[3]), "r"(b[0]), "r"(b[1]));
}
__device__ __forceinline__ unsigned ld_acq(const unsigned* p) {
    unsigned v;
    asm volatile("ld.global.acquire.gpu.u32 %0, [%1];" : "=r"(v) : "l"(p) : "memory");
    return v;
}
__device__ __forceinline__ void red_rel_add(unsigned* p, unsigned v) {
    asm volatile("red.release.gpu.global.add.u32 [%0], %1;" :: "l"(p), "r"(v) : "memory");
}

// ---------------- grid-wide barrier (single counter, load-polling) ----------------
__device__ __forceinline__ void gridbar(unsigned target) {
    __syncthreads();
    if (threadIdx.x == 0) {
        red_rel_add(&g_ctr, 1u);
        while (ld_acq(&g_ctr) < target) { }
    }
    __syncthreads();
}

// ---------------- resident-weight HMMA GEMM: 128x128 tile ----------------
// A [128][KF] global (staged K=64 chunks), B resident in smem (row stride BRS halves).
// S stages of K=64.  Partials written to Pp (+ n0 column offset), row length NFULL.
template <int S, int BRS, int NFULL>
__device__ __forceinline__ void gemm_res(const __half* __restrict__ A,
                                         const __half* __restrict__ sB,
                                         __half* __restrict__ sA,
                                         float* __restrict__ Pp,
                                         int n0, int kbase)
{
    const int tid = threadIdx.x, lane = tid & 31, wid = tid >> 5;
    const int wm = wid & 3, wn = wid >> 2;

    float acc[2][8][4];
    #pragma unroll
    for (int mt = 0; mt < 2; mt++)
        #pragma unroll
        for (int nt = 0; nt < 8; nt++)
            #pragma unroll
            for (int q = 0; q < 4; q++) acc[mt][nt][q] = 0.f;

    auto load_stage = [&](int s) {
        const int buf = s % 3;
        const int k0 = kbase + s * 64;
        __half* d = sA + buf * A_STG;
        #pragma unroll
        for (int i = 0; i < 4; i++) {
            int c = tid + i * 256;                 // 1024 16B chunks
            int r = c >> 3, j = c & 7;
            cp16(smem_u32(d + r * A_RS + j * 8), A + (size_t)r * KF + k0 + j * 8);
        }
        asm volatile("cp.async.commit_group;" ::: "memory");
    };

    load_stage(0);
    if (S > 1) load_stage(1);

    for (int s = 0; s < S; s++) {
        if (s + 1 < S) { asm volatile("cp.async.wait_group 1;" ::: "memory"); }
        else           { asm volatile("cp.async.wait_group 0;" ::: "memory"); }
        __syncthreads();
        if (s + 2 < S) load_stage(s + 2);

        const __half* bufA = sA + (s % 3) * A_STG;
        #pragma unroll
        for (int ks = 0; ks < 4; ks++) {           // 4 k16 steps per 64-K stage
            uint32_t a[2][4], b[8][2];
            #pragma unroll
            for (int mt = 0; mt < 2; mt++) {
                int row = wm * 32 + mt * 16 + (lane & 15);
                uint32_t ad = smem_u32(bufA + row * A_RS + ks * 16 + (lane >> 4) * 8);
                ldmx4(ad, a[mt][0], a[mt][1], a[mt][2], a[mt][3]);
            }
            #pragma unroll
            for (int q = 0; q < 4; q++) {
                int nr = wn * 64 + q * 16 + (lane >> 4) * 8 + (lane & 7);
                uint32_t bd = smem_u32(sB + nr * BRS + s * 64 + ks * 16 + ((lane >> 3) & 1) * 8);
                ldmx4(bd, b[2 * q][0], b[2 * q][1], b[2 * q + 1][0], b[2 * q + 1][1]);
            }
            #pragma unroll
            for (int mt = 0; mt < 2; mt++)
                #pragma unroll
                for (int nt = 0; nt < 8; nt++)
                    mma16816(acc[mt][nt], a[mt], b[nt]);
        }
    }

    float* Pb = Pp + n0;
    #pragma unroll
    for (int mt = 0; mt < 2; mt++) {
        int r = wm * 32 + mt * 16 + (lane >> 2);
        #pragma unroll
        for (int nt = 0; nt < 8; nt++) {
            int cc = wn * 64 + nt * 8 + (lane & 3) * 2;
            *(float2*)(Pb + (size_t)r * NFULL + cc)       = make_float2(acc[mt][nt][0], acc[mt][nt][1]);
            *(float2*)(Pb + (size_t)(r + 8) * NFULL + cc) = make_float2(acc[mt][nt][2], acc[mt][nt][3]);
        }
    }
}

// ---------------- old fully-staged GEMM body (used once for H0) ----------------
template <int KLOC, int NFULL>
__device__ __forceinline__ void gemm_body(const __half* __restrict__ A,
                                          const __half* __restrict__ B,
                                          float* __restrict__ Pp,
                                          int n0, int kbase,
                                          __half* sAb, __half* sBb)
{
    constexpr int S = KLOC / 32;
    const int tid = threadIdx.x, lane = tid & 31, wid = tid >> 5;
    const int wm = wid & 3, wn = wid >> 2;

    float acc[2][8][4];
    #pragma unroll
    for (int mt = 0; mt < 2; mt++)
        #pragma unroll
        for (int nt = 0; nt < 8; nt++)
            #pragma unroll
            for (int q = 0; q < 4; q++) acc[mt][nt][q] = 0.f;

    auto load_stage = [&](int s) {
        const int buf = s % 3;
        const int k0 = kbase + s * 32;
        __half* dA = sAb + buf * STAGE_H;
        __half* dB = sBb + buf * STAGE_H;
        {
            int r = tid >> 1, sub = (tid & 1) * 2;
            cp16(smem_u32(dA + r * RS + sub * 8),     A + (size_t)r * KF + k0 + sub * 8);
            cp16(smem_u32(dA + r * RS + sub * 8 + 8), A + (size_t)r * KF + k0 + sub * 8 + 8);
            cp16(smem_u32(dB + r * RS + sub * 8),     B + (size_t)(n0 + r) * KF + k0 + sub * 8);
            cp16(smem_u32(dB + r * RS + sub * 8 + 8), B + (size_t)(n0 + r) * KF + k0 + sub * 8 + 8);
        }
        asm volatile("cp.async.commit_group;" ::: "memory");
    };

    load_stage(0);
    load_stage(1);

    for (int s = 0; s < S; s++) {
        if (s + 1 < S) { asm volatile("cp.async.wait_group 1;" ::: "memory"); }
        else           { asm volatile("cp.async.wait_group 0;" ::: "memory"); }
        __syncthreads();
        if (s + 2 < S) load_stage(s + 2);

        const __half* bufA = sAb + (s % 3) * STAGE_H;
        const __half* bufB = sBb + (s % 3) * STAGE_H;
        #pragma unroll
        for (int ks = 0; ks < 2; ks++) {
            uint32_t a[2][4], b[8][2];
            #pragma unroll
            for (int mt = 0; mt < 2; mt++) {
                int row = wm * 32 + mt * 16 + (lane & 15);
                uint32_t ad = smem_u32(bufA + row * RS + ks * 16 + (lane >> 4) * 8);
                ldmx4(ad, a[mt][0], a[mt][1], a[mt][2], a[mt][3]);
            }
            #pragma unroll
            for (int q = 0; q < 4; q++) {
                int nr = wn * 64 + q * 16 + (lane >> 4) * 8 + (lane & 7);
                uint32_t bd = smem_u32(bufB + nr * RS + ks * 16 + ((lane >> 3) & 1) * 8);
                ldmx4(bd, b[2 * q][0], b[2 * q][1], b[2 * q + 1][0], b[2 * q + 1][1]);
            }
            #pragma unroll
            for (int mt = 0; mt < 2; mt++)
                #pragma unroll
                for (int nt = 0; nt < 8; nt++)
                    mma16816(acc[mt][nt], a[mt], b[nt]);
        }
    }

    float* Pb = Pp + n0;
    #pragma unroll
    for (int mt = 0; mt < 2; mt++) {
        int r = wm * 32 + mt * 16 + (lane >> 2);
        #pragma unroll
        for (int nt = 0; nt < 8; nt++) {
            int cc = wn * 64 + nt * 8 + (lane & 3) * 2;
            *(float2*)(Pb + (size_t)r * NFULL + cc)       = make_float2(acc[mt][nt][0], acc[mt][nt][1]);
            *(float2*)(Pb + (size_t)(r + 8) * NFULL + cc) = make_float2(acc[mt][nt][2], acc[mt][nt][3]);
        }
    }
}

template <int KLOC, int NFULL>
__global__ void __launch_bounds__(256) gemm_mma(const __half* __restrict__ A,
                                                const __half* __restrict__ B,
                                                float* __restrict__ P)
{
    extern __shared__ __align__(128) __half dynsm[];
    gemm_body<KLOC, NFULL>(A, B, P + (size_t)blockIdx.y * BATCH * NFULL,
                           blockIdx.x * 128, blockIdx.y * KLOC, dynsm, dynsm + 3 * STAGE_H);
}

// ---------------- elementwise helpers ----------------
__device__ __forceinline__ void f4_add(float4& a, const float4 b) {
    a.x += b.x; a.y += b.y; a.z += b.z; a.w += b.w;
}
__device__ __forceinline__ float4 f4_axpy(float al, const float4 a, const float4 b) {
    return make_float4(fmaf(al, a.x, b.x), fmaf(al, a.y, b.y), fmaf(al, a.z, b.z), fmaf(al, a.w, b.w));
}
__device__ __forceinline__ void lif_spike_reset(float4& m, float4& spk) {
    bool fx = (m.x - 1.0f) > 0.0f, fy = (m.y - 1.0f) > 0.0f;
    bool fz = (m.z - 1.0f) > 0.0f, fw = (m.w - 1.0f) > 0.0f;
    spk.x = fx ? 1.0f : 0.0f; if (fx) m.x = 0.0f;
    spk.y = fy ? 1.0f : 0.0f; if (fy) m.y = 0.0f;
    spk.z = fz ? 1.0f : 0.0f; if (fz) m.z = 0.0f;
    spk.w = fw ? 1.0f : 0.0f; if (fw) m.w = 0.0f;
}
__device__ __forceinline__ void store_spk_h(__half* base, int idx, const float4 spk) {
    __half2* sp = (__half2*)base;
    int m = idx >> 9, j = idx & 511;
    size_t o = (size_t)m * 2048 + j * 2;
    __half2 p0 = __floats2half2_rn(spk.x, spk.y);
    __half2 p1 = __floats2half2_rn(spk.z, spk.w);
    sp[o] = p0;        sp[o + 1] = p1;
    sp[o + 1024] = p0; sp[o + 1025] = p1;   // duplicate K half
}

// ---------------- persistent loop kernel ----------------
__global__ void __launch_bounds__(256, 1) persistent_loop(float* __restrict__ out)
{
    extern __shared__ __align__(128) __half dynsm[];
    __half* sW1 = dynsm + SW1_OFF;
    __half* sW2 = dynsm + SW2_OFF;
    __half* sA  = dynsm + SA_OFF;
    const int cta = blockIdx.x;
    const int tid = threadIdx.x;
    unsigned gen = 0;

    // CTA-owned tile coordinates (fixed for all steps)
    const int n0_1 = (cta & 15) * 128, kb_1 = (cta >> 4) * 512;   // GEMM1: 16 N x 8 K
    const int n0_2 = (cta & 3) * 128,  kb_2 = (cta >> 2) * 128;   // GEMM2: 4 N x 32 K

    // ---- load resident weight tiles once ----
    for (int c = tid; c < 8192; c += 256) {            // W1: 128 rows x 64 chunks
        int r = c >> 6, j = c & 63;
        cp16(smem_u32(sW1 + r * W1_RS + j * 8), g_W1Th + (size_t)(n0_1 + r) * KF + kb_1 + j * 8);
    }
    for (int c = tid; c < 2048; c += 256) {            // W2: 128 rows x 16 chunks
        int r = c >> 4, j = c & 15;
        cp16(smem_u32(sW2 + r * W2_RS + j * 8), g_W2Th + (size_t)(n0_2 + r) * KF + kb_2 + j * 8);
    }
    asm volatile("cp.async.commit_group;" ::: "memory");
    asm volatile("cp.async.wait_group 0;" ::: "memory");
    __syncthreads();

    for (int t = 0; t < TSTEPS; t++) {
        // ---- phase A: lif2(t-1) + GEMM1 ----
        if (t > 0 && tid < 128) {
            int idx = cta * 128 + tid;                       // f4 over [128][512]
            float4 h = make_float4(0.f, 0.f, 0.f, 0.f);
            #pragma unroll
            for (int ks = 0; ks < 32; ks++) f4_add(h, ((const float4*)g_p2)[(size_t)ks * 16384 + idx]);
            float4 s = f4_axpy(ALPHA_C, ((float4*)g_s2)[idx], h);
            float4 m = f4_axpy(BETA_C, ((float4*)g_m2)[idx], s);   // output layer: no reset
            ((float4*)g_s2)[idx] = s;
            ((float4*)g_m2)[idx] = m;
        }
        gemm_res<8, W1_RS, 2048>(g_spk0h, sW1, sA,
                                 g_p1 + (size_t)(cta >> 4) * BATCH * 2048, n0_1, kb_1);
        gridbar(++gen * NCTA);

        // ---- phase B: lif1 -> spk1 ; layer0 next-step -> spk0 ----
        #pragma unroll
        for (int r = 0; r < 2; r++) {
            int idx = cta * 512 + r * 256 + tid;             // f4 over [128][2048]
            float4 h = make_float4(0.f, 0.f, 0.f, 0.f);
            #pragma unroll
            for (int ks = 0; ks < 8; ks++) f4_add(h, ((const float4*)g_p1)[(size_t)ks * 65536 + idx]);
            float4 s = f4_axpy(ALPHA_C, ((float4*)g_s1)[idx], h);
            float4 m = f4_axpy(BETA_C, ((float4*)g_m1)[idx], s);
            float4 spk;
            lif_spike_reset(m, spk);
            ((float4*)g_s1)[idx] = s;
            ((float4*)g_m1)[idx] = m;
            store_spk_h(g_spk1h, idx, spk);
        }
        if (t + 1 < TSTEPS) {
            #pragma unroll
            for (int r = 0; r < 2; r++) {
                int idx = cta * 512 + r * 256 + tid;
                float4 m = f4_axpy(BETA_C, ((float4*)g_m0)[idx], ((float4*)g_H0)[idx]);
                float4 spk;
                lif_spike_reset(m, spk);
                ((float4*)g_m0)[idx] = m;
                store_spk_h(g_spk0h, idx, spk);
            }
        }
        gridbar(++gen * NCTA);

        // ---- phase C: GEMM2 (32 K-splits, KLOC=128, resident W2) ----
        gemm_res<2, W2_RS, 512>(g_spk1h, sW2, sA,
                                g_p2 + (size_t)(cta >> 2) * BATCH * 512, n0_2, kb_2);
        gridbar(++gen * NCTA);
    }

    // ---- final lif2 + output ----
    if (tid < 128) {
        int idx = cta * 128 + tid;
        float4 h = make_float4(0.f, 0.f, 0.f, 0.f);
        #pragma unroll
        for (int ks = 0; ks < 32; ks++) f4_add(h, ((const float4*)g_p2)[(size_t)ks * 16384 + idx]);
        float4 s = f4_axpy(ALPHA_C, ((float4*)g_s2)[idx], h);
        float4 m = f4_axpy(BETA_C, ((float4*)g_m2)[idx], s);
        ((float4*)out)[idx] = m;
    }
}

// ---------------- one-time prep kernels ----------------
__global__ void conv_w(const float* __restrict__ W, __half* __restrict__ WT, int N)
{
    __shared__ float t[32][33];
    const int k0 = blockIdx.x * 32, nb = blockIdx.y * 32;
    const int tx = threadIdx.x, ty = threadIdx.y;
    for (int i = ty; i < 32; i += 8)
        t[i][tx] = W[(size_t)(k0 + i) * N + nb + tx];
    __syncthreads();
    if (tx < 16) {
        for (int n2 = ty; n2 < 32; n2 += 8) {
            float w0 = t[2 * tx][n2], w1 = t[2 * tx + 1][n2];
            __half h0 = __float2half_rn(w0), h1 = __float2half_rn(w1);
            __half l0 = __float2half_rn(w0 - __half2float(h0));
            __half l1 = __float2half_rn(w1 - __half2float(h1));
            size_t row = (size_t)(nb + n2) * KF;
            ((__half2*)(WT + row + k0))[tx]        = __halves2half2(h0, h1);
            ((__half2*)(WT + row + 2048 + k0))[tx] = __halves2half2(l0, l1);
        }
    }
}

__global__ void conv_w0(const float* __restrict__ W, __half* __restrict__ WT)
{
    __shared__ float t[32][33];
    const int k0 = blockIdx.x * 32, nb = blockIdx.y * 32;
    const int tx = threadIdx.x, ty = threadIdx.y;
    for (int i = ty; i < 32; i += 8)
        t[i][tx] = W[(size_t)(k0 + i) * 2048 + nb + tx];
    __syncthreads();
    if (tx < 16) {
        for (int n2 = ty; n2 < 32; n2 += 8) {
            float w0 = t[2 * tx][n2], w1 = t[2 * tx + 1][n2];
            __half h0 = __float2half_rn(w0), h1 = __float2half_rn(w1);
            __half l0 = __float2half_rn(w0 - __half2float(h0));
            __half l1 = __float2half_rn(w1 - __half2float(h1));
            size_t row = (size_t)(nb + n2) * KF;
            __half2 hh = __halves2half2(h0, h1);
            ((__half2*)(WT + row + k0))[tx]        = hh;                        // seg0: hi
            ((__half2*)(WT + row + 1024 + k0))[tx] = hh;                        // seg1: hi
            ((__half2*)(WT + row + 2048 + k0))[tx] = __halves2half2(l0, l1);    // seg2: lo
            ((__half2*)(WT + row + 3072 + k0))[tx] = __halves2half2(__float2half_rn(0.f), __float2half_rn(0.f));
        }
    }
}

__global__ void split_input(const float* __restrict__ inp)
{
    int g = blockIdx.x * blockDim.x + threadIdx.x;     // < 131072
    int m = g >> 10, k = g & 1023;
    float v = inp[g];
    __half hi = __float2half_rn(v);
    __half lo = __float2half_rn(v - __half2float(hi));
    size_t row = (size_t)m * KF;
    g_inh[row + k] = hi;
    g_inh[row + 1024 + k] = lo;
    g_inh[row + 2048 + k] = hi;
    g_inh[row + 3072 + k] = __float2half_rn(0.f);
}

__global__ void reduce0()
{
    int idx = blockIdx.x * blockDim.x + threadIdx.x;   // < 65536
    float4 h = make_float4(0.f, 0.f, 0.f, 0.f);
#pragma unroll
    for (int ks = 0; ks < 8; ks++) f4_add(h, ((const float4*)g_p1)[(size_t)ks * 65536 + idx]);
    ((float4*)g_H0)[idx] = h;
    float4 m = h, spk;
    lif_spike_reset(m, spk);
    ((float4*)g_m0)[idx] = m;
    store_spk_h(g_spk0h, idx, spk);
}

__global__ void init_states()
{
    int idx = blockIdx.x * blockDim.x + threadIdx.x;   // < 65536
    float4 z = make_float4(0.f, 0.f, 0.f, 0.f);
    ((float4*)g_s1)[idx] = z;
    ((float4*)g_m1)[idx] = z;
    if (idx < BATCH * N2 / 4) { ((float4*)g_s2)[idx] = z; ((float4*)g_m2)[idx] = z; }
    if (idx == 0) g_ctr = 0u;
}

// ---------------- launch ----------------
extern "C" void kernel_launch(void* const* d_in, const int* in_sizes, int n_in,
                              void* d_out, int out_size)
{
    const float* inp = nullptr; const float* W0 = nullptr;
    const float* W1 = nullptr;  const float* W2 = nullptr;
    for (int i = 0; i < n_in; i++) {
        switch (in_sizes[i]) {
            case BATCH * K0: inp = (const float*)d_in[i]; break;
            case K0 * N0:    W0  = (const float*)d_in[i]; break;
            case 2048 * N1:  W1  = (const float*)d_in[i]; break;
            case 2048 * N2:  W2  = (const float*)d_in[i]; break;
        }
    }

    float* p1;
    __half *inh, *w0t, *w1t, *w2t;
    cudaGetSymbolAddress((void**)&p1,  g_p1);
    cudaGetSymbolAddress((void**)&inh, g_inh);
    cudaGetSymbolAddress((void**)&w0t, g_W0Th);
    cudaGetSymbolAddress((void**)&w1t, g_W1Th);
    cudaGetSymbolAddress((void**)&w2t, g_W2Th);

    static bool attr_done = false;
    if (!attr_done) {
        cudaFuncSetAttribute(gemm_mma<512, 2048>, cudaFuncAttributeMaxDynamicSharedMemorySize, H0_SMEM_BYTES);
        cudaFuncSetAttribute(persistent_loop, cudaFuncAttributeMaxDynamicSharedMemorySize, PERS_SMEM_BYTES);
        attr_done = true;
    }

    init_states<<<256, 256>>>();
    conv_w0<<<dim3(32, 64), dim3(32, 8)>>>(W0, w0t);
    conv_w<<<dim3(64, 64), dim3(32, 8)>>>(W1, w1t, N1);
    conv_w<<<dim3(64, 16), dim3(32, 8)>>>(W2, w2t, N2);
    split_input<<<512, 256>>>(inp);

    // H0 = inputs @ W0 via HMMA (8 K-splits), then reduce + step-0 layer0
    gemm_mma<512, 2048><<<dim3(16, 8), 256, H0_SMEM_BYTES>>>(inh, w0t, p1);
    reduce0<<<256, 256>>>();

    // all 50 timesteps in one persistent kernel
    persistent_loop<<<NCTA, 256, PERS_SMEM_BYTES>>>((float*)d_out);
}

// round 11
// speedup vs baseline: 3.5227x; 1.0640x over previous
#include <cuda_runtime.h>
#include <cuda_fp16.h>
#include <cstdint>

#define BATCH 128
#define N0 2048
#define N1 2048
#define N2 512
#define K0 1024
#define KF 4096            // hi|lo concatenated K dimension
#define ALPHA_C 0.9f
#define BETA_C  0.85f
#define TSTEPS 50
#define NCTA 128

// ---- H0 standalone GEMM staging ----
#define RS 40
#define STAGE_H (128 * RS)
#define H0_SMEM_BYTES (3 * STAGE_H * 2 * 2)      // 61440

// ---- persistent kernel smem layout (halves) ----
#define W1_RS 520                                 // 512 + 8 pad
#define W2_RS 136                                 // 128 + 8 pad
#define A_RS  72                                  // 64 + 8 pad
#define A_STG (128 * A_RS)                        // 9216 halves / stage
#define SW1_OFF 0
#define SW2_OFF (128 * W1_RS)                     // 66560
#define SA_OFF  (SW2_OFF + 128 * W2_RS)           // 83968
#define PERS_SMEM_BYTES ((SA_OFF + 3 * A_STG) * 2)  // 223232 B

// ---------------- static device scratch ----------------
__device__ float g_H0[BATCH * N0];
__device__ float g_m0[BATCH * N0];
__device__ float g_s1[BATCH * N1];
__device__ float g_m1[BATCH * N1];
__device__ float g_s2[BATCH * N2];
__device__ float g_m2[BATCH * N2];
__device__ __half g_spk0h[BATCH * KF];     // layer0 spikes fp16, duplicated halves
__device__ __half g_spk1h[BATCH * KF];     // layer1 spikes fp16, duplicated halves
__device__ __half g_inh[BATCH * KF];       // input ext: [hi | lo | hi | 0]
__device__ __half g_W0Th[N0 * KF];         // [n][k]: [hiW | hiW | loW | 0]
__device__ __half g_W1Th[N1 * KF];         // [n][k]: k<2048 hi, k>=2048 lo
__device__ __half g_W2Th[N2 * KF];
__device__ float g_p1[8 * BATCH * N1];     // split-K partials (H0 GEMM / GEMM1)
__device__ float g_p2[32 * BATCH * N2];    // split-K partials GEMM2
__device__ unsigned g_ctr;                 // grid barrier counter

// ---------------- PTX helpers ----------------
__device__ __forceinline__ uint32_t smem_u32(const void* p) {
    uint32_t a;
    asm("{ .reg .u64 t; cvta.to.shared.u64 t, %1; cvt.u32.u64 %0, t; }" : "=r"(a) : "l"(p));
    return a;
}
__device__ __forceinline__ void cp16(uint32_t dst, const void* src) {
    asm volatile("cp.async.cg.shared.global [%0], [%1], 16;" :: "r"(dst), "l"(src));
}
__device__ __forceinline__ void ldmx4(uint32_t addr, uint32_t& r0, uint32_t& r1,
                                      uint32_t& r2, uint32_t& r3) {
    asm volatile("ldmatrix.sync.aligned.m8n8.x4.shared.b16 {%0,%1,%2,%3}, [%4];"
                 : "=r"(r0), "=r"(r1), "=r"(r2), "=r"(r3) : "r"(addr));
}
__device__ __forceinline__ void mma16816(float* d, const uint32_t* a, const uint32_t* b) {
    asm volatile(
        "mma.sync.aligned.m16n8k16.row.col.f32.f16.f16.f32 "
        "{%0,%1,%2,%3}, {%4,%5,%6,%7}, {%8,%9}, {%0,%1,%2,%3};"
        : "+f"(d[0]), "+f"(d[1]), "+f"(d[2]), "+f"(d[3])
        : "r"(a[0]), "r"(a[1]), "r"(a[2]), "r"(a[3]), "r"(b[0]), "r"(b[1]));
}
__device__ __forceinline__ unsigned ld_acq(const unsigned* p) {
    unsigned v;
    asm volatile("ld.global.acquire.gpu.u32 %0, [%1];" : "=r"(v) : "l"(p) : "memory");
    return v;
}
__device__ __forceinline__ void red_rel_add(unsigned* p, unsigned v) {
    asm volatile("red.release.gpu.global.add.u32 [%0], %1;" :: "l"(p), "r"(v) : "memory");
}

// ---------------- grid-wide barrier (single counter, load-polling) ----------------
__device__ __forceinline__ void gridbar(unsigned target) {
    __syncthreads();
    if (threadIdx.x == 0) {
        red_rel_add(&g_ctr, 1u);
        while (ld_acq(&g_ctr) < target) { }
    }
    __syncthreads();
}

// ---------------- resident-weight HMMA GEMM: 128x128 tile ----------------
// A [128][KF] global (staged K=64 chunks), B resident in smem (row stride BRS halves).
template <int S, int BRS, int NFULL>
__device__ __forceinline__ void gemm_res(const __half* __restrict__ A,
                                         const __half* __restrict__ sB,
                                         __half* __restrict__ sA,
                                         float* __restrict__ Pp,
                                         int n0, int kbase)
{
    const int tid = threadIdx.x, lane = tid & 31, wid = tid >> 5;
    const int wm = wid & 3, wn = wid >> 2;

    float acc[2][8][4];
    #pragma unroll
    for (int mt = 0; mt < 2; mt++)
        #pragma unroll
        for (int nt = 0; nt < 8; nt++)
            #pragma unroll
            for (int q = 0; q < 4; q++) acc[mt][nt][q] = 0.f;

    auto load_stage = [&](int s) {
        const int buf = s % 3;
        const int k0 = kbase + s * 64;
        __half* d = sA + buf * A_STG;
        #pragma unroll
        for (int i = 0; i < 4; i++) {
            int c = tid + i * 256;                 // 1024 16B chunks
            int r = c >> 3, j = c & 7;
            cp16(smem_u32(d + r * A_RS + j * 8), A + (size_t)r * KF + k0 + j * 8);
        }
        asm volatile("cp.async.commit_group;" ::: "memory");
    };

    load_stage(0);
    if (S > 1) load_stage(1);

    for (int s = 0; s < S; s++) {
        if (s + 1 < S) { asm volatile("cp.async.wait_group 1;" ::: "memory"); }
        else           { asm volatile("cp.async.wait_group 0;" ::: "memory"); }
        __syncthreads();
        if (s + 2 < S) load_stage(s + 2);

        const __half* bufA = sA + (s % 3) * A_STG;
        #pragma unroll
        for (int ks = 0; ks < 4; ks++) {           // 4 k16 steps per 64-K stage
            uint32_t a[2][4], b[8][2];
            #pragma unroll
            for (int mt = 0; mt < 2; mt++) {
                int row = wm * 32 + mt * 16 + (lane & 15);
                uint32_t ad = smem_u32(bufA + row * A_RS + ks * 16 + (lane >> 4) * 8);
                ldmx4(ad, a[mt][0], a[mt][1], a[mt][2], a[mt][3]);
            }
            #pragma unroll
            for (int q = 0; q < 4; q++) {
                int nr = wn * 64 + q * 16 + (lane >> 4) * 8 + (lane & 7);
                uint32_t bd = smem_u32(sB + nr * BRS + s * 64 + ks * 16 + ((lane >> 3) & 1) * 8);
                ldmx4(bd, b[2 * q][0], b[2 * q][1], b[2 * q + 1][0], b[2 * q + 1][1]);
            }
            #pragma unroll
            for (int mt = 0; mt < 2; mt++)
                #pragma unroll
                for (int nt = 0; nt < 8; nt++)
                    mma16816(acc[mt][nt], a[mt], b[nt]);
        }
    }
    __syncthreads();          // protect A staging buffers before next gemm reuses them

    float* Pb = Pp + n0;
    #pragma unroll
    for (int mt = 0; mt < 2; mt++) {
        int r = wm * 32 + mt * 16 + (lane >> 2);
        #pragma unroll
        for (int nt = 0; nt < 8; nt++) {
            int cc = wn * 64 + nt * 8 + (lane & 3) * 2;
            *(float2*)(Pb + (size_t)r * NFULL + cc)       = make_float2(acc[mt][nt][0], acc[mt][nt][1]);
            *(float2*)(Pb + (size_t)(r + 8) * NFULL + cc) = make_float2(acc[mt][nt][2], acc[mt][nt][3]);
        }
    }
}

// ---------------- fully-staged GEMM body (used once for H0) ----------------
template <int KLOC, int NFULL>
__device__ __forceinline__ void gemm_body(const __half* __restrict__ A,
                                          const __half* __restrict__ B,
                                          float* __restrict__ Pp,
                                          int n0, int kbase,
                                          __half* sAb, __half* sBb)
{
    constexpr int S = KLOC / 32;
    const int tid = threadIdx.x, lane = tid & 31, wid = tid >> 5;
    const int wm = wid & 3, wn = wid >> 2;

    float acc[2][8][4];
    #pragma unroll
    for (int mt = 0; mt < 2; mt++)
        #pragma unroll
        for (int nt = 0; nt < 8; nt++)
            #pragma unroll
            for (int q = 0; q < 4; q++) acc[mt][nt][q] = 0.f;

    auto load_stage = [&](int s) {
        const int buf = s % 3;
        const int k0 = kbase + s * 32;
        __half* dA = sAb + buf * STAGE_H;
        __half* dB = sBb + buf * STAGE_H;
        {
            int r = tid >> 1, sub = (tid & 1) * 2;
            cp16(smem_u32(dA + r * RS + sub * 8),     A + (size_t)r * KF + k0 + sub * 8);
            cp16(smem_u32(dA + r * RS + sub * 8 + 8), A + (size_t)r * KF + k0 + sub * 8 + 8);
            cp16(smem_u32(dB + r * RS + sub * 8),     B + (size_t)(n0 + r) * KF + k0 + sub * 8);
            cp16(smem_u32(dB + r * RS + sub * 8 + 8), B + (size_t)(n0 + r) * KF + k0 + sub * 8 + 8);
        }
        asm volatile("cp.async.commit_group;" ::: "memory");
    };

    load_stage(0);
    load_stage(1);

    for (int s = 0; s < S; s++) {
        if (s + 1 < S) { asm volatile("cp.async.wait_group 1;" ::: "memory"); }
        else           { asm volatile("cp.async.wait_group 0;" ::: "memory"); }
        __syncthreads();
        if (s + 2 < S) load_stage(s + 2);

        const __half* bufA = sAb + (s % 3) * STAGE_H;
        const __half* bufB = sBb + (s % 3) * STAGE_H;
        #pragma unroll
        for (int ks = 0; ks < 2; ks++) {
            uint32_t a[2][4], b[8][2];
            #pragma unroll
            for (int mt = 0; mt < 2; mt++) {
                int row = wm * 32 + mt * 16 + (lane & 15);
                uint32_t ad = smem_u32(bufA + row * RS + ks * 16 + (lane >> 4) * 8);
                ldmx4(ad, a[mt][0], a[mt][1], a[mt][2], a[mt][3]);
            }
            #pragma unroll
            for (int q = 0; q < 4; q++) {
                int nr = wn * 64 + q * 16 + (lane >> 4) * 8 + (lane & 7);
                uint32_t bd = smem_u32(bufB + nr * RS + ks * 16 + ((lane >> 3) & 1) * 8);
                ldmx4(bd, b[2 * q][0], b[2 * q][1], b[2 * q + 1][0], b[2 * q + 1][1]);
            }
            #pragma unroll
            for (int mt = 0; mt < 2; mt++)
                #pragma unroll
                for (int nt = 0; nt < 8; nt++)
                    mma16816(acc[mt][nt], a[mt], b[nt]);
        }
    }

    float* Pb = Pp + n0;
    #pragma unroll
    for (int mt = 0; mt < 2; mt++) {
        int r = wm * 32 + mt * 16 + (lane >> 2);
        #pragma unroll
        for (int nt = 0; nt < 8; nt++) {
            int cc = wn * 64 + nt * 8 + (lane & 3) * 2;
            *(float2*)(Pb + (size_t)r * NFULL + cc)       = make_float2(acc[mt][nt][0], acc[mt][nt][1]);
            *(float2*)(Pb + (size_t)(r + 8) * NFULL + cc) = make_float2(acc[mt][nt][2], acc[mt][nt][3]);
        }
    }
}

template <int KLOC, int NFULL>
__global__ void __launch_bounds__(256) gemm_mma(const __half* __restrict__ A,
                                                const __half* __restrict__ B,
                                                float* __restrict__ P)
{
    extern __shared__ __align__(128) __half dynsm[];
    gemm_body<KLOC, NFULL>(A, B, P + (size_t)blockIdx.y * BATCH * NFULL,
                           blockIdx.x * 128, blockIdx.y * KLOC, dynsm, dynsm + 3 * STAGE_H);
}

// ---------------- elementwise helpers ----------------
__device__ __forceinline__ void f4_add(float4& a, const float4 b) {
    a.x += b.x; a.y += b.y; a.z += b.z; a.w += b.w;
}
__device__ __forceinline__ float4 f4_axpy(float al, const float4 a, const float4 b) {
    return make_float4(fmaf(al, a.x, b.x), fmaf(al, a.y, b.y), fmaf(al, a.z, b.z), fmaf(al, a.w, b.w));
}
__device__ __forceinline__ void lif_spike_reset(float4& m, float4& spk) {
    bool fx = (m.x - 1.0f) > 0.0f, fy = (m.y - 1.0f) > 0.0f;
    bool fz = (m.z - 1.0f) > 0.0f, fw = (m.w - 1.0f) > 0.0f;
    spk.x = fx ? 1.0f : 0.0f; if (fx) m.x = 0.0f;
    spk.y = fy ? 1.0f : 0.0f; if (fy) m.y = 0.0f;
    spk.z = fz ? 1.0f : 0.0f; if (fz) m.z = 0.0f;
    spk.w = fw ? 1.0f : 0.0f; if (fw) m.w = 0.0f;
}
__device__ __forceinline__ void store_spk_h(__half* base, int idx, const float4 spk) {
    __half2* sp = (__half2*)base;
    int m = idx >> 9, j = idx & 511;
    size_t o = (size_t)m * 2048 + j * 2;
    __half2 p0 = __floats2half2_rn(spk.x, spk.y);
    __half2 p1 = __floats2half2_rn(spk.z, spk.w);
    sp[o] = p0;        sp[o + 1] = p1;
    sp[o + 1024] = p0; sp[o + 1025] = p1;   // duplicate K half
}

// ---------------- persistent loop kernel: 2-phase schedule ----------------
__global__ void __launch_bounds__(256, 1) persistent_loop(float* __restrict__ out)
{
    extern __shared__ __align__(128) __half dynsm[];
    __half* sW1 = dynsm + SW1_OFF;
    __half* sW2 = dynsm + SW2_OFF;
    __half* sA  = dynsm + SA_OFF;
    const int cta = blockIdx.x;
    const int tid = threadIdx.x;
    unsigned gen = 0;

    const int n0_1 = (cta & 15) * 128, kb_1 = (cta >> 4) * 512;   // GEMM1: 16 N x 8 K
    const int n0_2 = (cta & 3) * 128,  kb_2 = (cta >> 2) * 128;   // GEMM2: 4 N x 32 K

    // ---- load resident weight tiles once ----
    for (int c = tid; c < 8192; c += 256) {            // W1: 128 rows x 64 chunks
        int r = c >> 6, j = c & 63;
        cp16(smem_u32(sW1 + r * W1_RS + j * 8), g_W1Th + (size_t)(n0_1 + r) * KF + kb_1 + j * 8);
    }
    for (int c = tid; c < 2048; c += 256) {            // W2: 128 rows x 16 chunks
        int r = c >> 4, j = c & 15;
        cp16(smem_u32(sW2 + r * W2_RS + j * 8), g_W2Th + (size_t)(n0_2 + r) * KF + kb_2 + j * 8);
    }
    asm volatile("cp.async.commit_group;" ::: "memory");
    asm volatile("cp.async.wait_group 0;" ::: "memory");
    __syncthreads();

    for (int t = 0; t < TSTEPS; t++) {
        // ---- phase X: GEMM1(t) + GEMM2(t-1) ----
        gemm_res<8, W1_RS, 2048>(g_spk0h, sW1, sA,
                                 g_p1 + (size_t)(cta >> 4) * BATCH * 2048, n0_1, kb_1);
        if (t > 0)
            gemm_res<2, W2_RS, 512>(g_spk1h, sW2, sA,
                                    g_p2 + (size_t)(cta >> 2) * BATCH * 512, n0_2, kb_2);
        gridbar(++gen * NCTA);

        // ---- phase Y: lif1(t) -> spk1 ; l0 -> spk0(t+1) ; lif2(t-1) ----
        #pragma unroll
        for (int r = 0; r < 2; r++) {
            int idx = cta * 512 + r * 256 + tid;             // f4 over [128][2048]
            float4 h = make_float4(0.f, 0.f, 0.f, 0.f);
            #pragma unroll
            for (int ks = 0; ks < 8; ks++) f4_add(h, ((const float4*)g_p1)[(size_t)ks * 65536 + idx]);
            float4 s = f4_axpy(ALPHA_C, ((float4*)g_s1)[idx], h);
            float4 m = f4_axpy(BETA_C, ((float4*)g_m1)[idx], s);
            float4 spk;
            lif_spike_reset(m, spk);
            ((float4*)g_s1)[idx] = s;
            ((float4*)g_m1)[idx] = m;
            store_spk_h(g_spk1h, idx, spk);
        }
        if (t + 1 < TSTEPS) {
            #pragma unroll
            for (int r = 0; r < 2; r++) {
                int idx = cta * 512 + r * 256 + tid;
                float4 m = f4_axpy(BETA_C, ((float4*)g_m0)[idx], ((float4*)g_H0)[idx]);
                float4 spk;
                lif_spike_reset(m, spk);
                ((float4*)g_m0)[idx] = m;
                store_spk_h(g_spk0h, idx, spk);
            }
        }
        if (t > 0 && tid < 128) {
            int idx = cta * 128 + tid;                       // f4 over [128][512]
            float4 h = make_float4(0.f, 0.f, 0.f, 0.f);
            #pragma unroll
            for (int ks = 0; ks < 32; ks++) f4_add(h, ((const float4*)g_p2)[(size_t)ks * 16384 + idx]);
            float4 s = f4_axpy(ALPHA_C, ((float4*)g_s2)[idx], h);
            float4 m = f4_axpy(BETA_C, ((float4*)g_m2)[idx], s);   // output layer: no reset
            ((float4*)g_s2)[idx] = s;
            ((float4*)g_m2)[idx] = m;
        }
        gridbar(++gen * NCTA);
    }

    // ---- tail: GEMM2(T-1), then final lif2 + output ----
    gemm_res<2, W2_RS, 512>(g_spk1h, sW2, sA,
                            g_p2 + (size_t)(cta >> 2) * BATCH * 512, n0_2, kb_2);
    gridbar(++gen * NCTA);

    if (tid < 128) {
        int idx = cta * 128 + tid;
        float4 h = make_float4(0.f, 0.f, 0.f, 0.f);
        #pragma unroll
        for (int ks = 0; ks < 32; ks++) f4_add(h, ((const float4*)g_p2)[(size_t)ks * 16384 + idx]);
        float4 s = f4_axpy(ALPHA_C, ((float4*)g_s2)[idx], h);
        float4 m = f4_axpy(BETA_C, ((float4*)g_m2)[idx], s);
        ((float4*)out)[idx] = m;
    }
}

// ---------------- one-time prep kernels ----------------
__global__ void conv_w(const float* __restrict__ W, __half* __restrict__ WT, int N)
{
    __shared__ float t[32][33];
    const int k0 = blockIdx.x * 32, nb = blockIdx.y * 32;
    const int tx = threadIdx.x, ty = threadIdx.y;
    for (int i = ty; i < 32; i += 8)
        t[i][tx] = W[(size_t)(k0 + i) * N + nb + tx];
    __syncthreads();
    if (tx < 16) {
        for (int n2 = ty; n2 < 32; n2 += 8) {
            float w0 = t[2 * tx][n2], w1 = t[2 * tx + 1][n2];
            __half h0 = __float2half_rn(w0), h1 = __float2half_rn(w1);
            __half l0 = __float2half_rn(w0 - __half2float(h0));
            __half l1 = __float2half_rn(w1 - __half2float(h1));
            size_t row = (size_t)(nb + n2) * KF;
            ((__half2*)(WT + row + k0))[tx]        = __halves2half2(h0, h1);
            ((__half2*)(WT + row + 2048 + k0))[tx] = __halves2half2(l0, l1);
        }
    }
}

__global__ void conv_w0(const float* __restrict__ W, __half* __restrict__ WT)
{
    __shared__ float t[32][33];
    const int k0 = blockIdx.x * 32, nb = blockIdx.y * 32;
    const int tx = threadIdx.x, ty = threadIdx.y;
    for (int i = ty; i < 32; i += 8)
        t[i][tx] = W[(size_t)(k0 + i) * 2048 + nb + tx];
    __syncthreads();
    if (tx < 16) {
        for (int n2 = ty; n2 < 32; n2 += 8) {
            float w0 = t[2 * tx][n2], w1 = t[2 * tx + 1][n2];
            __half h0 = __float2half_rn(w0), h1 = __float2half_rn(w1);
            __half l0 = __float2half_rn(w0 - __half2float(h0));
            __half l1 = __float2half_rn(w1 - __half2float(h1));
            size_t row = (size_t)(nb + n2) * KF;
            __half2 hh = __halves2half2(h0, h1);
            ((__half2*)(WT + row + k0))[tx]        = hh;                        // seg0: hi
            ((__half2*)(WT + row + 1024 + k0))[tx] = hh;                        // seg1: hi
            ((__half2*)(WT + row + 2048 + k0))[tx] = __halves2half2(l0, l1);    // seg2: lo
            ((__half2*)(WT + row + 3072 + k0))[tx] = __halves2half2(__float2half_rn(0.f), __float2half_rn(0.f));
        }
    }
}

__global__ void split_input(const float* __restrict__ inp)
{
    int g = blockIdx.x * blockDim.x + threadIdx.x;     // < 131072
    int m = g >> 10, k = g & 1023;
    float v = inp[g];
    __half hi = __float2half_rn(v);
    __half lo = __float2half_rn(v - __half2float(hi));
    size_t row = (size_t)m * KF;
    g_inh[row + k] = hi;
    g_inh[row + 1024 + k] = lo;
    g_inh[row + 2048 + k] = hi;
    g_inh[row + 3072 + k] = __float2half_rn(0.f);
}

__global__ void reduce0()
{
    int idx = blockIdx.x * blockDim.x + threadIdx.x;   // < 65536
    float4 h = make_float4(0.f, 0.f, 0.f, 0.f);
#pragma unroll
    for (int ks = 0; ks < 8; ks++) f4_add(h, ((const float4*)g_p1)[(size_t)ks * 65536 + idx]);
    ((float4*)g_H0)[idx] = h;
    float4 m = h, spk;
    lif_spike_reset(m, spk);
    ((float4*)g_m0)[idx] = m;
    store_spk_h(g_spk0h, idx, spk);
}

__global__ void init_states()
{
    int idx = blockIdx.x * blockDim.x + threadIdx.x;   // < 65536
    float4 z = make_float4(0.f, 0.f, 0.f, 0.f);
    ((float4*)g_s1)[idx] = z;
    ((float4*)g_m1)[idx] = z;
    if (idx < BATCH * N2 / 4) { ((float4*)g_s2)[idx] = z; ((float4*)g_m2)[idx] = z; }
    if (idx == 0) g_ctr = 0u;
}

// ---------------- launch ----------------
extern "C" void kernel_launch(void* const* d_in, const int* in_sizes, int n_in,
                              void* d_out, int out_size)
{
    const float* inp = nullptr; const float* W0 = nullptr;
    const float* W1 = nullptr;  const float* W2 = nullptr;
    for (int i = 0; i < n_in; i++) {
        switch (in_sizes[i]) {
            case BATCH * K0: inp = (const float*)d_in[i]; break;
            case K0 * N0:    W0  = (const float*)d_in[i]; break;
            case 2048 * N1:  W1  = (const float*)d_in[i]; break;
            case 2048 * N2:  W2  = (const float*)d_in[i]; break;
        }
    }

    float* p1;
    __half *inh, *w0t, *w1t, *w2t;
    cudaGetSymbolAddress((void**)&p1,  g_p1);
    cudaGetSymbolAddress((void**)&inh, g_inh);
    cudaGetSymbolAddress((void**)&w0t, g_W0Th);
    cudaGetSymbolAddress((void**)&w1t, g_W1Th);
    cudaGetSymbolAddress((void**)&w2t, g_W2Th);

    static bool attr_done = false;
    if (!attr_done) {
        cudaFuncSetAttribute(gemm_mma<512, 2048>, cudaFuncAttributeMaxDynamicSharedMemorySize, H0_SMEM_BYTES);
        cudaFuncSetAttribute(persistent_loop, cudaFuncAttributeMaxDynamicSharedMemorySize, PERS_SMEM_BYTES);
        attr_done = true;
    }

    init_states<<<256, 256>>>();
    conv_w0<<<dim3(32, 64), dim3(32, 8)>>>(W0, w0t);
    conv_w<<<dim3(64, 64), dim3(32, 8)>>>(W1, w1t, N1);
    conv_w<<<dim3(64, 16), dim3(32, 8)>>>(W2, w2t, N2);
    split_input<<<512, 256>>>(inp);

    // H0 = inputs @ W0 via HMMA (8 K-splits), then reduce + step-0 layer0
    gemm_mma<512, 2048><<<dim3(16, 8), 256, H0_SMEM_BYTES>>>(inh, w0t, p1);
    reduce0<<<256, 256>>>();

    // all 50 timesteps in one persistent kernel
    persistent_loop<<<NCTA, 256, PERS_SMEM_BYTES>>>((float*)d_out);
}

// round 12
// speedup vs baseline: 3.5250x; 1.0007x over previous
#include <cuda_runtime.h>
#include <cuda_fp16.h>
#include <cstdint>

#define BATCH 128
#define N0 2048
#define N1 2048
#define N2 512
#define K0 1024
#define KF 4096            // hi|lo concatenated K dimension (weights)
#define KS 2048            // spike storage stride (un-duplicated)
#define ALPHA_C 0.9f
#define BETA_C  0.85f
#define TSTEPS 50
#define NCTA 128

// ---- H0 standalone GEMM staging ----
#define RS 40
#define STAGE_H (128 * RS)
#define H0_SMEM_BYTES (3 * STAGE_H * 2 * 2)      // 61440

// ---- persistent kernel smem layout (halves) ----
#define W1_RS 520                                 // 512 + 8 pad
#define W2_RS 136                                 // 128 + 8 pad
#define A_RS  72                                  // 64 + 8 pad
#define A_STG (128 * A_RS)                        // 9216 halves / stage
#define SW1_OFF 0
#define SW2_OFF (128 * W1_RS)                     // 66560
#define SA_OFF  (SW2_OFF + 128 * W2_RS)           // 83968
#define PERS_SMEM_BYTES ((SA_OFF + 3 * A_STG) * 2)  // 223232 B

// ---------------- static device scratch ----------------
__device__ float g_H0[BATCH * N0];
__device__ float g_m0[BATCH * N0];
__device__ float g_s1[BATCH * N1];
__device__ float g_m1[BATCH * N1];
__device__ float g_s2[BATCH * N2];
__device__ float g_m2[BATCH * N2];
__device__ __half g_spk0h[2][BATCH * KS];  // layer0 spikes fp16, double-buffered
__device__ __half g_spk1h[BATCH * KS];     // layer1 spikes fp16
__device__ __half g_inh[BATCH * KF];       // input ext: [hi | lo | hi | 0]
__device__ __half g_W0Th[N0 * KF];         // [n][k]: [hiW | hiW | loW | 0]
__device__ __half g_W1Th[N1 * KF];         // [n][k]: k<2048 hi, k>=2048 lo
__device__ __half g_W2Th[N2 * KF];
__device__ float g_p1[8 * BATCH * N1];     // split-K partials (H0 GEMM / GEMM1)
__device__ float g_p2[32 * BATCH * N2];    // split-K partials GEMM2
__device__ unsigned g_ctr;                 // grid barrier counter

// ---------------- PTX helpers ----------------
__device__ __forceinline__ uint32_t smem_u32(const void* p) {
    uint32_t a;
    asm("{ .reg .u64 t; cvta.to.shared.u64 t, %1; cvt.u32.u64 %0, t; }" : "=r"(a) : "l"(p));
    return a;
}
__device__ __forceinline__ void cp16(uint32_t dst, const void* src) {
    asm volatile("cp.async.cg.shared.global [%0], [%1], 16;" :: "r"(dst), "l"(src));
}
__device__ __forceinline__ void ldmx4(uint32_t addr, uint32_t& r0, uint32_t& r1,
                                      uint32_t& r2, uint32_t& r3) {
    asm volatile("ldmatrix.sync.aligned.m8n8.x4.shared.b16 {%0,%1,%2,%3}, [%4];"
                 : "=r"(r0), "=r"(r1), "=r"(r2), "=r"(r3) : "r"(addr));
}
__device__ __forceinline__ void mma16816(float* d, const uint32_t* a, const uint32_t* b) {
    asm volatile(
        "mma.sync.aligned.m16n8k16.row.col.f32.f16.f16.f32 "
        "{%0,%1,%2,%3}, {%4,%5,%6,%7}, {%8,%9}, {%0,%1,%2,%3};"
        : "+f"(d[0]), "+f"(d[1]), "+f"(d[2]), "+f"(d[3])
        : "r"(a[0]), "r"(a[1]), "r"(a[2]), "r"(a[3]), "r"(b[0]), "r"(b[1]));
}
__device__ __forceinline__ unsigned ld_acq(const unsigned* p) {
    unsigned v;
    asm volatile("ld.global.acquire.gpu.u32 %0, [%1];" : "=r"(v) : "l"(p) : "memory");
    return v;
}
__device__ __forceinline__ void red_rel_add(unsigned* p, unsigned v) {
    asm volatile("red.release.gpu.global.add.u32 [%0], %1;" :: "l"(p), "r"(v) : "memory");
}

// ---------------- grid-wide barrier ----------------
__device__ __forceinline__ void gridbar(unsigned target) {
    __syncthreads();
    if (threadIdx.x == 0) {
        red_rel_add(&g_ctr, 1u);
        while (ld_acq(&g_ctr) < target) { }
    }
    __syncthreads();
}

// ---------------- resident-weight HMMA GEMM: 128x128 tile ----------------
// A base pre-offset to this CTA's K-window; row stride ASTR halves.
template <int S, int BRS, int NFULL, int ASTR>
__device__ __forceinline__ void gemm_res(const __half* __restrict__ A,
                                         const __half* __restrict__ sB,
                                         __half* __restrict__ sA,
                                         float* __restrict__ Pp,
                                         int n0)
{
    const int tid = threadIdx.x, lane = tid & 31, wid = tid >> 5;
    const int wm = wid & 3, wn = wid >> 2;

    float acc[2][8][4];
    #pragma unroll
    for (int mt = 0; mt < 2; mt++)
        #pragma unroll
        for (int nt = 0; nt < 8; nt++)
            #pragma unroll
            for (int q = 0; q < 4; q++) acc[mt][nt][q] = 0.f;

    auto load_stage = [&](int s) {
        const int buf = s % 3;
        const int k0 = s * 64;
        __half* d = sA + buf * A_STG;
        #pragma unroll
        for (int i = 0; i < 4; i++) {
            int c = tid + i * 256;                 // 1024 16B chunks
            int r = c >> 3, j = c & 7;
            cp16(smem_u32(d + r * A_RS + j * 8), A + (size_t)r * ASTR + k0 + j * 8);
        }
        asm volatile("cp.async.commit_group;" ::: "memory");
    };

    load_stage(0);
    if (S > 1) load_stage(1);

    for (int s = 0; s < S; s++) {
        if (s + 1 < S) { asm volatile("cp.async.wait_group 1;" ::: "memory"); }
        else           { asm volatile("cp.async.wait_group 0;" ::: "memory"); }
        __syncthreads();
        if (s + 2 < S) load_stage(s + 2);

        const __half* bufA = sA + (s % 3) * A_STG;
        #pragma unroll
        for (int ks = 0; ks < 4; ks++) {           // 4 k16 steps per 64-K stage
            uint32_t a[2][4], b[8][2];
            #pragma unroll
            for (int mt = 0; mt < 2; mt++) {
                int row = wm * 32 + mt * 16 + (lane & 15);
                uint32_t ad = smem_u32(bufA + row * A_RS + ks * 16 + (lane >> 4) * 8);
                ldmx4(ad, a[mt][0], a[mt][1], a[mt][2], a[mt][3]);
            }
            #pragma unroll
            for (int q = 0; q < 4; q++) {
                int nr = wn * 64 + q * 16 + (lane >> 4) * 8 + (lane & 7);
                uint32_t bd = smem_u32(sB + nr * BRS + s * 64 + ks * 16 + ((lane >> 3) & 1) * 8);
                ldmx4(bd, b[2 * q][0], b[2 * q][1], b[2 * q + 1][0], b[2 * q + 1][1]);
            }
            #pragma unroll
            for (int mt = 0; mt < 2; mt++)
                #pragma unroll
                for (int nt = 0; nt < 8; nt++)
                    mma16816(acc[mt][nt], a[mt], b[nt]);
        }
    }
    __syncthreads();          // protect A staging buffers before next gemm reuses them

    float* Pb = Pp + n0;
    #pragma unroll
    for (int mt = 0; mt < 2; mt++) {
        int r = wm * 32 + mt * 16 + (lane >> 2);
        #pragma unroll
        for (int nt = 0; nt < 8; nt++) {
            int cc = wn * 64 + nt * 8 + (lane & 3) * 2;
            *(float2*)(Pb + (size_t)r * NFULL + cc)       = make_float2(acc[mt][nt][0], acc[mt][nt][1]);
            *(float2*)(Pb + (size_t)(r + 8) * NFULL + cc) = make_float2(acc[mt][nt][2], acc[mt][nt][3]);
        }
    }
}

// ---------------- fully-staged GEMM body (used once for H0, KF strides) ----------------
template <int KLOC, int NFULL>
__device__ __forceinline__ void gemm_body(const __half* __restrict__ A,
                                          const __half* __restrict__ B,
                                          float* __restrict__ Pp,
                                          int n0, int kbase,
                                          __half* sAb, __half* sBb)
{
    constexpr int S = KLOC / 32;
    const int tid = threadIdx.x, lane = tid & 31, wid = tid >> 5;
    const int wm = wid & 3, wn = wid >> 2;

    float acc[2][8][4];
    #pragma unroll
    for (int mt = 0; mt < 2; mt++)
        #pragma unroll
        for (int nt = 0; nt < 8; nt++)
            #pragma unroll
            for (int q = 0; q < 4; q++) acc[mt][nt][q] = 0.f;

    auto load_stage = [&](int s) {
        const int buf = s % 3;
        const int k0 = kbase + s * 32;
        __half* dA = sAb + buf * STAGE_H;
        __half* dB = sBb + buf * STAGE_H;
        {
            int r = tid >> 1, sub = (tid & 1) * 2;
            cp16(smem_u32(dA + r * RS + sub * 8),     A + (size_t)r * KF + k0 + sub * 8);
            cp16(smem_u32(dA + r * RS + sub * 8 + 8), A + (size_t)r * KF + k0 + sub * 8 + 8);
            cp16(smem_u32(dB + r * RS + sub * 8),     B + (size_t)(n0 + r) * KF + k0 + sub * 8);
            cp16(smem_u32(dB + r * RS + sub * 8 + 8), B + (size_t)(n0 + r) * KF + k0 + sub * 8 + 8);
        }
        asm volatile("cp.async.commit_group;" ::: "memory");
    };

    load_stage(0);
    load_stage(1);

    for (int s = 0; s < S; s++) {
        if (s + 1 < S) { asm volatile("cp.async.wait_group 1;" ::: "memory"); }
        else           { asm volatile("cp.async.wait_group 0;" ::: "memory"); }
        __syncthreads();
        if (s + 2 < S) load_stage(s + 2);

        const __half* bufA = sAb + (s % 3) * STAGE_H;
        const __half* bufB = sBb + (s % 3) * STAGE_H;
        #pragma unroll
        for (int ks = 0; ks < 2; ks++) {
            uint32_t a[2][4], b[8][2];
            #pragma unroll
            for (int mt = 0; mt < 2; mt++) {
                int row = wm * 32 + mt * 16 + (lane & 15);
                uint32_t ad = smem_u32(bufA + row * RS + ks * 16 + (lane >> 4) * 8);
                ldmx4(ad, a[mt][0], a[mt][1], a[mt][2], a[mt][3]);
            }
            #pragma unroll
            for (int q = 0; q < 4; q++) {
                int nr = wn * 64 + q * 16 + (lane >> 4) * 8 + (lane & 7);
                uint32_t bd = smem_u32(bufB + nr * RS + ks * 16 + ((lane >> 3) & 1) * 8);
                ldmx4(bd, b[2 * q][0], b[2 * q][1], b[2 * q + 1][0], b[2 * q + 1][1]);
            }
            #pragma unroll
            for (int mt = 0; mt < 2; mt++)
                #pragma unroll
                for (int nt = 0; nt < 8; nt++)
                    mma16816(acc[mt][nt], a[mt], b[nt]);
        }
    }

    float* Pb = Pp + n0;
    #pragma unroll
    for (int mt = 0; mt < 2; mt++) {
        int r = wm * 32 + mt * 16 + (lane >> 2);
        #pragma unroll
        for (int nt = 0; nt < 8; nt++) {
            int cc = wn * 64 + nt * 8 + (lane & 3) * 2;
            *(float2*)(Pb + (size_t)r * NFULL + cc)       = make_float2(acc[mt][nt][0], acc[mt][nt][1]);
            *(float2*)(Pb + (size_t)(r + 8) * NFULL + cc) = make_float2(acc[mt][nt][2], acc[mt][nt][3]);
        }
    }
}

template <int KLOC, int NFULL>
__global__ void __launch_bounds__(256) gemm_mma(const __half* __restrict__ A,
                                                const __half* __restrict__ B,
                                                float* __restrict__ P)
{
    extern __shared__ __align__(128) __half dynsm[];
    gemm_body<KLOC, NFULL>(A, B, P + (size_t)blockIdx.y * BATCH * NFULL,
                           blockIdx.x * 128, blockIdx.y * KLOC, dynsm, dynsm + 3 * STAGE_H);
}

// ---------------- elementwise helpers ----------------
__device__ __forceinline__ void f4_add(float4& a, const float4 b) {
    a.x += b.x; a.y += b.y; a.z += b.z; a.w += b.w;
}
__device__ __forceinline__ float4 f4_axpy(float al, const float4 a, const float4 b) {
    return make_float4(fmaf(al, a.x, b.x), fmaf(al, a.y, b.y), fmaf(al, a.z, b.z), fmaf(al, a.w, b.w));
}
__device__ __forceinline__ void lif_spike_reset(float4& m, float4& spk) {
    bool fx = (m.x - 1.0f) > 0.0f, fy = (m.y - 1.0f) > 0.0f;
    bool fz = (m.z - 1.0f) > 0.0f, fw = (m.w - 1.0f) > 0.0f;
    spk.x = fx ? 1.0f : 0.0f; if (fx) m.x = 0.0f;
    spk.y = fy ? 1.0f : 0.0f; if (fy) m.y = 0.0f;
    spk.z = fz ? 1.0f : 0.0f; if (fz) m.z = 0.0f;
    spk.w = fw ? 1.0f : 0.0f; if (fw) m.w = 0.0f;
}
// 4 spikes -> single 8B store (idx = float4 index over [128][2048])
__device__ __forceinline__ void store_spk_h(__half* base, int idx, const float4 spk) {
    __half2 p0 = __floats2half2_rn(spk.x, spk.y);
    __half2 p1 = __floats2half2_rn(spk.z, spk.w);
    unsigned long long v = (unsigned long long)(*(unsigned*)&p0)
                         | ((unsigned long long)(*(unsigned*)&p1) << 32);
    ((unsigned long long*)base)[idx] = v;
}

// ---------------- persistent loop kernel: 2-phase schedule ----------------
__global__ void __launch_bounds__(256, 1) persistent_loop(float* __restrict__ out)
{
    extern __shared__ __align__(128) __half dynsm[];
    __half* sW1 = dynsm + SW1_OFF;
    __half* sW2 = dynsm + SW2_OFF;
    __half* sA  = dynsm + SA_OFF;
    const int cta = blockIdx.x;
    const int tid = threadIdx.x;
    unsigned gen = 0;

    const int n0_1 = (cta & 15) * 128, kb_1 = (cta >> 4) * 512;   // GEMM1: 16 N x 8 K
    const int n0_2 = (cta & 3) * 128,  kb_2 = (cta >> 2) * 128;   // GEMM2: 4 N x 32 K
    const int ka_1 = kb_1 & (KS - 1);                             // spike window offsets
    const int ka_2 = kb_2 & (KS - 1);

    // ---- load resident weight tiles once ----
    for (int c = tid; c < 8192; c += 256) {            // W1: 128 rows x 64 chunks
        int r = c >> 6, j = c & 63;
        cp16(smem_u32(sW1 + r * W1_RS + j * 8), g_W1Th + (size_t)(n0_1 + r) * KF + kb_1 + j * 8);
    }
    for (int c = tid; c < 2048; c += 256) {            // W2: 128 rows x 16 chunks
        int r = c >> 4, j = c & 15;
        cp16(smem_u32(sW2 + r * W2_RS + j * 8), g_W2Th + (size_t)(n0_2 + r) * KF + kb_2 + j * 8);
    }
    asm volatile("cp.async.commit_group;" ::: "memory");
    asm volatile("cp.async.wait_group 0;" ::: "memory");
    __syncthreads();

    for (int t = 0; t < TSTEPS; t++) {
        // ---- phase X: GEMM1(t) + GEMM2(t-1) + l0 update(t+1) ----
        gemm_res<8, W1_RS, 2048, KS>(g_spk0h[t & 1] + ka_1, sW1, sA,
                                     g_p1 + (size_t)(cta >> 4) * BATCH * 2048, n0_1);
        if (t > 0)
            gemm_res<2, W2_RS, 512, KS>(g_spk1h + ka_2, sW2, sA,
                                        g_p2 + (size_t)(cta >> 2) * BATCH * 512, n0_2);
        if (t + 1 < TSTEPS) {
            __half* spknext = g_spk0h[(t + 1) & 1];
            #pragma unroll
            for (int r = 0; r < 2; r++) {
                int idx = cta * 512 + r * 256 + tid;           // f4 over [128][2048]
                float4 m = f4_axpy(BETA_C, ((float4*)g_m0)[idx], ((float4*)g_H0)[idx]);
                float4 spk;
                lif_spike_reset(m, spk);
                ((float4*)g_m0)[idx] = m;
                store_spk_h(spknext, idx, spk);
            }
        }
        gridbar(++gen * NCTA);

        // ---- phase Y: lif1(t) -> spk1 ; lif2(t-1) ----
        #pragma unroll
        for (int r = 0; r < 2; r++) {
            int idx = cta * 512 + r * 256 + tid;               // f4 over [128][2048]
            float4 h = make_float4(0.f, 0.f, 0.f, 0.f);
            #pragma unroll
            for (int ks = 0; ks < 8; ks++) f4_add(h, ((const float4*)g_p1)[(size_t)ks * 65536 + idx]);
            float4 s = f4_axpy(ALPHA_C, ((float4*)g_s1)[idx], h);
            float4 m = f4_axpy(BETA_C, ((float4*)g_m1)[idx], s);
            float4 spk;
            lif_spike_reset(m, spk);
            ((float4*)g_s1)[idx] = s;
            ((float4*)g_m1)[idx] = m;
            store_spk_h(g_spk1h, idx, spk);
        }
        if (t > 0 && tid < 128) {
            int idx = cta * 128 + tid;                         // f4 over [128][512]
            float4 h = make_float4(0.f, 0.f, 0.f, 0.f);
            #pragma unroll
            for (int ks = 0; ks < 32; ks++) f4_add(h, ((const float4*)g_p2)[(size_t)ks * 16384 + idx]);
            float4 s = f4_axpy(ALPHA_C, ((float4*)g_s2)[idx], h);
            float4 m = f4_axpy(BETA_C, ((float4*)g_m2)[idx], s);   // output layer: no reset
            ((float4*)g_s2)[idx] = s;
            ((float4*)g_m2)[idx] = m;
        }
        gridbar(++gen * NCTA);
    }

    // ---- tail: GEMM2(T-1), then final lif2 + output ----
    gemm_res<2, W2_RS, 512, KS>(g_spk1h + ka_2, sW2, sA,
                                g_p2 + (size_t)(cta >> 2) * BATCH * 512, n0_2);
    gridbar(++gen * NCTA);

    if (tid < 128) {
        int idx = cta * 128 + tid;
        float4 h = make_float4(0.f, 0.f, 0.f, 0.f);
        #pragma unroll
        for (int ks = 0; ks < 32; ks++) f4_add(h, ((const float4*)g_p2)[(size_t)ks * 16384 + idx]);
        float4 s = f4_axpy(ALPHA_C, ((float4*)g_s2)[idx], h);
        float4 m = f4_axpy(BETA_C, ((float4*)g_m2)[idx], s);
        ((float4*)out)[idx] = m;
    }
}

// ---------------- one-time prep kernels ----------------
__global__ void conv_w(const float* __restrict__ W, __half* __restrict__ WT, int N)
{
    __shared__ float t[32][33];
    const int k0 = blockIdx.x * 32, nb = blockIdx.y * 32;
    const int tx = threadIdx.x, ty = threadIdx.y;
    for (int i = ty; i < 32; i += 8)
        t[i][tx] = W[(size_t)(k0 + i) * N + nb + tx];
    __syncthreads();
    if (tx < 16) {
        for (int n2 = ty; n2 < 32; n2 += 8) {
            float w0 = t[2 * tx][n2], w1 = t[2 * tx + 1][n2];
            __half h0 = __float2half_rn(w0), h1 = __float2half_rn(w1);
            __half l0 = __float2half_rn(w0 - __half2float(h0));
            __half l1 = __float2half_rn(w1 - __half2float(h1));
            size_t row = (size_t)(nb + n2) * KF;
            ((__half2*)(WT + row + k0))[tx]        = __halves2half2(h0, h1);
            ((__half2*)(WT + row + 2048 + k0))[tx] = __halves2half2(l0, l1);
        }
    }
}

__global__ void conv_w0(const float* __restrict__ W, __half* __restrict__ WT)
{
    __shared__ float t[32][33];
    const int k0 = blockIdx.x * 32, nb = blockIdx.y * 32;
    const int tx = threadIdx.x, ty = threadIdx.y;
    for (int i = ty; i < 32; i += 8)
        t[i][tx] = W[(size_t)(k0 + i) * 2048 + nb + tx];
    __syncthreads();
    if (tx < 16) {
        for (int n2 = ty; n2 < 32; n2 += 8) {
            float w0 = t[2 * tx][n2], w1 = t[2 * tx + 1][n2];
            __half h0 = __float2half_rn(w0), h1 = __float2half_rn(w1);
            __half l0 = __float2half_rn(w0 - __half2float(h0));
            __half l1 = __float2half_rn(w1 - __half2float(h1));
            size_t row = (size_t)(nb + n2) * KF;
            __half2 hh = __halves2half2(h0, h1);
            ((__half2*)(WT + row + k0))[tx]        = hh;                        // seg0: hi
            ((__half2*)(WT + row + 1024 + k0))[tx] = hh;                        // seg1: hi
            ((__half2*)(WT + row + 2048 + k0))[tx] = __halves2half2(l0, l1);    // seg2: lo
            ((__half2*)(WT + row + 3072 + k0))[tx] = __halves2half2(__float2half_rn(0.f), __float2half_rn(0.f));
        }
    }
}

__global__ void split_input(const float* __restrict__ inp)
{
    int g = blockIdx.x * blockDim.x + threadIdx.x;     // < 131072
    int m = g >> 10, k = g & 1023;
    float v = inp[g];
    __half hi = __float2half_rn(v);
    __half lo = __float2half_rn(v - __half2float(hi));
    size_t row = (size_t)m * KF;
    g_inh[row + k] = hi;
    g_inh[row + 1024 + k] = lo;
    g_inh[row + 2048 + k] = hi;
    g_inh[row + 3072 + k] = __float2half_rn(0.f);
}

__global__ void reduce0()
{
    int idx = blockIdx.x * blockDim.x + threadIdx.x;   // < 65536
    float4 h = make_float4(0.f, 0.f, 0.f, 0.f);
#pragma unroll
    for (int ks = 0; ks < 8; ks++) f4_add(h, ((const float4*)g_p1)[(size_t)ks * 65536 + idx]);
    ((float4*)g_H0)[idx] = h;
    float4 m = h, spk;
    lif_spike_reset(m, spk);
    ((float4*)g_m0)[idx] = m;
    store_spk_h(g_spk0h[0], idx, spk);
}

__global__ void init_states()
{
    int idx = blockIdx.x * blockDim.x + threadIdx.x;   // < 65536
    float4 z = make_float4(0.f, 0.f, 0.f, 0.f);
    ((float4*)g_s1)[idx] = z;
    ((float4*)g_m1)[idx] = z;
    if (idx < BATCH * N2 / 4) { ((float4*)g_s2)[idx] = z; ((float4*)g_m2)[idx] = z; }
    if (idx == 0) g_ctr = 0u;
}

// ---------------- launch ----------------
extern "C" void kernel_launch(void* const* d_in, const int* in_sizes, int n_in,
                              void* d_out, int out_size)
{
    const float* inp = nullptr; const float* W0 = nullptr;
    const float* W1 = nullptr;  const float* W2 = nullptr;
    for (int i = 0; i < n_in; i++) {
        switch (in_sizes[i]) {
            case BATCH * K0: inp = (const float*)d_in[i]; break;
            case K0 * N0:    W0  = (const float*)d_in[i]; break;
            case 2048 * N1:  W1  = (const float*)d_in[i]; break;
            case 2048 * N2:  W2  = (const float*)d_in[i]; break;
        }
    }

    float* p1;
    __half *inh, *w0t, *w1t, *w2t;
    cudaGetSymbolAddress((void**)&p1,  g_p1);
    cudaGetSymbolAddress((void**)&inh, g_inh);
    cudaGetSymbolAddress((void**)&w0t, g_W0Th);
    cudaGetSymbolAddress((void**)&w1t, g_W1Th);
    cudaGetSymbolAddress((void**)&w2t, g_W2Th);

    static bool attr_done = false;
    if (!attr_done) {
        cudaFuncSetAttribute(gemm_mma<512, 2048>, cudaFuncAttributeMaxDynamicSharedMemorySize, H0_SMEM_BYTES);
        cudaFuncSetAttribute(persistent_loop, cudaFuncAttributeMaxDynamicSharedMemorySize, PERS_SMEM_BYTES);
        attr_done = true;
    }

    init_states<<<256, 256>>>();
    conv_w0<<<dim3(32, 64), dim3(32, 8)>>>(W0, w0t);
    conv_w<<<dim3(64, 64), dim3(32, 8)>>>(W1, w1t, N1);
    conv_w<<<dim3(64, 16), dim3(32, 8)>>>(W2, w2t, N2);
    split_input<<<512, 256>>>(inp);

    // H0 = inputs @ W0 via HMMA (8 K-splits), then reduce + step-0 layer0
    gemm_mma<512, 2048><<<dim3(16, 8), 256, H0_SMEM_BYTES>>>(inh, w0t, p1);
    reduce0<<<256, 256>>>();

    // all 50 timesteps in one persistent kernel
    persistent_loop<<<NCTA, 256, PERS_SMEM_BYTES>>>((float*)d_out);
}

// round 13
// speedup vs baseline: 3.8164x; 1.0827x over previous
#include <cuda_runtime.h>
#include <cuda_fp16.h>
#include <cstdint>

#define BATCH 128
#define N0 2048
#define N1 2048
#define N2 512
#define K0 1024
#define KF 4096            // hi|lo concatenated K dimension (weights)
#define KS 2048            // spike storage stride
#define ALPHA_C 0.9f
#define BETA_C  0.85f
#define TSTEPS 50
#define NCTA 128

// ---- H0 standalone GEMM staging ----
#define RS 40
#define STAGE_H (128 * RS)
#define H0_SMEM_BYTES (3 * STAGE_H * 2 * 2)      // 61440

// ---- persistent kernel smem layout (halves) ----
#define W1_RS 520                                 // 512 + 8 pad (128-wide tile, K_loc 512)
#define W2_RS 264                                 // 256 + 8 pad (64-wide tile, K_loc 256)
#define A_RS  72                                  // 64 + 8 pad
#define A_STG (128 * A_RS)                        // 9216 halves / stage
#define SW1_OFF 0
#define SW2_OFF (128 * W1_RS)                     // 66560
#define SA_OFF  (SW2_OFF + 64 * W2_RS)            // 83456
#define PERS_SMEM_BYTES ((SA_OFF + 3 * A_STG) * 2)  // 222208 B

// ---------------- static device scratch ----------------
__device__ float g_H0[BATCH * N0];
__device__ float g_m0[BATCH * N0];
__device__ float g_s1[BATCH * N1];
__device__ float g_m1[BATCH * N1];
__device__ float g_s2[BATCH * N2];
__device__ float g_m2[BATCH * N2];
__device__ __half g_spk0h[2][BATCH * KS];  // layer0 spikes fp16, double-buffered
__device__ __half g_spk1h[BATCH * KS];     // layer1 spikes fp16
__device__ __half g_inh[BATCH * KF];       // input ext: [hi | lo | hi | 0]
__device__ __half g_W0Th[N0 * KF];         // [n][k]: [hiW | hiW | loW | 0]
__device__ __half g_W1Th[N1 * KF];         // [n][k]: k<2048 hi, k>=2048 lo
__device__ __half g_W2Th[N2 * KF];
__device__ float g_p1[8 * BATCH * N1];     // split-K partials (H0 GEMM 8 / GEMM1 8)
__device__ float g_p2[16 * BATCH * N2];    // split-K partials GEMM2 (16)
__device__ unsigned g_ctr;                 // grid barrier counter

// ---------------- PTX helpers ----------------
__device__ __forceinline__ uint32_t smem_u32(const void* p) {
    uint32_t a;
    asm("{ .reg .u64 t; cvta.to.shared.u64 t, %1; cvt.u32.u64 %0, t; }" : "=r"(a) : "l"(p));
    return a;
}
__device__ __forceinline__ void cp16(uint32_t dst, const void* src) {
    asm volatile("cp.async.cg.shared.global [%0], [%1], 16;" :: "r"(dst), "l"(src));
}
__device__ __forceinline__ void ldmx4(uint32_t addr, uint32_t& r0, uint32_t& r1,
                                      uint32_t& r2, uint32_t& r3) {
    asm volatile("ldmatrix.sync.aligned.m8n8.x4.shared.b16 {%0,%1,%2,%3}, [%4];"
                 : "=r"(r0), "=r"(r1), "=r"(r2), "=r"(r3) : "r"(addr));
}
__device__ __forceinline__ void mma16816(float* d, const uint32_t* a, const uint32_t* b) {
    asm volatile(
        "mma.sync.aligned.m16n8k16.row.col.f32.f16.f16.f32 "
        "{%0,%1,%2,%3}, {%4,%5,%6,%7}, {%8,%9}, {%0,%1,%2,%3};"
        : "+f"(d[0]), "+f"(d[1]), "+f"(d[2]), "+f"(d[3])
        : "r"(a[0]), "r"(a[1]), "r"(a[2]), "r"(a[3]), "r"(b[0]), "r"(b[1]));
}
__device__ __forceinline__ unsigned ld_acq(const unsigned* p) {
    unsigned v;
    asm volatile("ld.global.acquire.gpu.u32 %0, [%1];" : "=r"(v) : "l"(p) : "memory");
    return v;
}
__device__ __forceinline__ void red_rel_add(unsigned* p, unsigned v) {
    asm volatile("red.release.gpu.global.add.u32 [%0], %1;" :: "l"(p), "r"(v) : "memory");
}

// ---------------- grid-wide barrier ----------------
__device__ __forceinline__ void gridbar(unsigned target) {
    __syncthreads();
    if (threadIdx.x == 0) {
        red_rel_add(&g_ctr, 1u);
        while (ld_acq(&g_ctr) < target) { }
    }
    __syncthreads();
}

// ---------------- A-stage loader (128 rows x 64 k, triple-buffered ring) ----------------
__device__ __forceinline__ void stage_A(const __half* __restrict__ A, __half* __restrict__ sA, int s) {
    const int tid = threadIdx.x;
    const int buf = s % 3;
    const int k0 = s * 64;
    __half* d = sA + buf * A_STG;
    #pragma unroll
    for (int i = 0; i < 4; i++) {
        int c = tid + i * 256;                 // 1024 16B chunks
        int r = c >> 3, j = c & 7;
        cp16(smem_u32(d + r * A_RS + j * 8), A + (size_t)r * KS + k0 + j * 8);
    }
    asm volatile("cp.async.commit_group;" ::: "memory");
}

// ---------------- resident-weight HMMA GEMM: 128x128 tile ----------------
template <int S, int BRS, int NFULL>
__device__ __forceinline__ void gemm_res128(const __half* __restrict__ A,
                                            const __half* __restrict__ sB,
                                            __half* __restrict__ sA,
                                            float* __restrict__ Pp,
                                            int n0, int preloaded)
{
    const int tid = threadIdx.x, lane = tid & 31, wid = tid >> 5;
    const int wm = wid & 3, wn = wid >> 2;

    float acc[2][8][4];
    #pragma unroll
    for (int mt = 0; mt < 2; mt++)
        #pragma unroll
        for (int nt = 0; nt < 8; nt++)
            #pragma unroll
            for (int q = 0; q < 4; q++) acc[mt][nt][q] = 0.f;

    if (preloaded < 1) stage_A(A, sA, 0);
    if (S > 1 && preloaded < 2) stage_A(A, sA, 1);

    for (int s = 0; s < S; s++) {
        if (s + 1 < S) { asm volatile("cp.async.wait_group 1;" ::: "memory"); }
        else           { asm volatile("cp.async.wait_group 0;" ::: "memory"); }
        __syncthreads();
        if (s + 2 < S) stage_A(A, sA, s + 2);

        const __half* bufA = sA + (s % 3) * A_STG;
        #pragma unroll
        for (int ks = 0; ks < 4; ks++) {
            uint32_t a[2][4], b[8][2];
            #pragma unroll
            for (int mt = 0; mt < 2; mt++) {
                int row = wm * 32 + mt * 16 + (lane & 15);
                uint32_t ad = smem_u32(bufA + row * A_RS + ks * 16 + (lane >> 4) * 8);
                ldmx4(ad, a[mt][0], a[mt][1], a[mt][2], a[mt][3]);
            }
            #pragma unroll
            for (int q = 0; q < 4; q++) {
                int nr = wn * 64 + q * 16 + (lane >> 4) * 8 + (lane & 7);
                uint32_t bd = smem_u32(sB + nr * BRS + s * 64 + ks * 16 + ((lane >> 3) & 1) * 8);
                ldmx4(bd, b[2 * q][0], b[2 * q][1], b[2 * q + 1][0], b[2 * q + 1][1]);
            }
            #pragma unroll
            for (int mt = 0; mt < 2; mt++)
                #pragma unroll
                for (int nt = 0; nt < 8; nt++)
                    mma16816(acc[mt][nt], a[mt], b[nt]);
        }
    }
    __syncthreads();

    float* Pb = Pp + n0;
    #pragma unroll
    for (int mt = 0; mt < 2; mt++) {
        int r = wm * 32 + mt * 16 + (lane >> 2);
        #pragma unroll
        for (int nt = 0; nt < 8; nt++) {
            int cc = wn * 64 + nt * 8 + (lane & 3) * 2;
            *(float2*)(Pb + (size_t)r * NFULL + cc)       = make_float2(acc[mt][nt][0], acc[mt][nt][1]);
            *(float2*)(Pb + (size_t)(r + 8) * NFULL + cc) = make_float2(acc[mt][nt][2], acc[mt][nt][3]);
        }
    }
}

// ---------------- resident-weight HMMA GEMM: 128x64 tile (GEMM2) ----------------
template <int S, int BRS, int NFULL>
__device__ __forceinline__ void gemm_res64(const __half* __restrict__ A,
                                           const __half* __restrict__ sB,
                                           __half* __restrict__ sA,
                                           float* __restrict__ Pp,
                                           int n0)
{
    const int tid = threadIdx.x, lane = tid & 31, wid = tid >> 5;
    const int wm = wid & 3, wn = wid >> 2;          // wn in {0,1}: 32-col halves

    float acc[2][4][4];
    #pragma unroll
    for (int mt = 0; mt < 2; mt++)
        #pragma unroll
        for (int nt = 0; nt < 4; nt++)
            #pragma unroll
            for (int q = 0; q < 4; q++) acc[mt][nt][q] = 0.f;

    stage_A(A, sA, 0);
    if (S > 1) stage_A(A, sA, 1);

    for (int s = 0; s < S; s++) {
        if (s + 1 < S) { asm volatile("cp.async.wait_group 1;" ::: "memory"); }
        else           { asm volatile("cp.async.wait_group 0;" ::: "memory"); }
        __syncthreads();
        if (s + 2 < S) stage_A(A, sA, s + 2);

        const __half* bufA = sA + (s % 3) * A_STG;
        #pragma unroll
        for (int ks = 0; ks < 4; ks++) {
            uint32_t a[2][4], b[4][2];
            #pragma unroll
            for (int mt = 0; mt < 2; mt++) {
                int row = wm * 32 + mt * 16 + (lane & 15);
                uint32_t ad = smem_u32(bufA + row * A_RS + ks * 16 + (lane >> 4) * 8);
                ldmx4(ad, a[mt][0], a[mt][1], a[mt][2], a[mt][3]);
            }
            #pragma unroll
            for (int q = 0; q < 2; q++) {
                int nr = wn * 32 + q * 16 + (lane >> 4) * 8 + (lane & 7);
                uint32_t bd = smem_u32(sB + nr * BRS + s * 64 + ks * 16 + ((lane >> 3) & 1) * 8);
                ldmx4(bd, b[2 * q][0], b[2 * q][1], b[2 * q + 1][0], b[2 * q + 1][1]);
            }
            #pragma unroll
            for (int mt = 0; mt < 2; mt++)
                #pragma unroll
                for (int nt = 0; nt < 4; nt++)
                    mma16816(acc[mt][nt], a[mt], b[nt]);
        }
    }
    __syncthreads();

    float* Pb = Pp + n0;
    #pragma unroll
    for (int mt = 0; mt < 2; mt++) {
        int r = wm * 32 + mt * 16 + (lane >> 2);
        #pragma unroll
        for (int nt = 0; nt < 4; nt++) {
            int cc = wn * 32 + nt * 8 + (lane & 3) * 2;
            *(float2*)(Pb + (size_t)r * NFULL + cc)       = make_float2(acc[mt][nt][0], acc[mt][nt][1]);
            *(float2*)(Pb + (size_t)(r + 8) * NFULL + cc) = make_float2(acc[mt][nt][2], acc[mt][nt][3]);
        }
    }
}

// ---------------- fully-staged GEMM body (used once for H0, KF strides) ----------------
template <int KLOC, int NFULL>
__device__ __forceinline__ void gemm_body(const __half* __restrict__ A,
                                          const __half* __restrict__ B,
                                          float* __restrict__ Pp,
                                          int n0, int kbase,
                                          __half* sAb, __half* sBb)
{
    constexpr int S = KLOC / 32;
    const int tid = threadIdx.x, lane = tid & 31, wid = tid >> 5;
    const int wm = wid & 3, wn = wid >> 2;

    float acc[2][8][4];
    #pragma unroll
    for (int mt = 0; mt < 2; mt++)
        #pragma unroll
        for (int nt = 0; nt < 8; nt++)
            #pragma unroll
            for (int q = 0; q < 4; q++) acc[mt][nt][q] = 0.f;

    auto load_stage = [&](int s) {
        const int buf = s % 3;
        const int k0 = kbase + s * 32;
        __half* dA = sAb + buf * STAGE_H;
        __half* dB = sBb + buf * STAGE_H;
        {
            int r = tid >> 1, sub = (tid & 1) * 2;
            cp16(smem_u32(dA + r * RS + sub * 8),     A + (size_t)r * KF + k0 + sub * 8);
            cp16(smem_u32(dA + r * RS + sub * 8 + 8), A + (size_t)r * KF + k0 + sub * 8 + 8);
            cp16(smem_u32(dB + r * RS + sub * 8),     B + (size_t)(n0 + r) * KF + k0 + sub * 8);
            cp16(smem_u32(dB + r * RS + sub * 8 + 8), B + (size_t)(n0 + r) * KF + k0 + sub * 8 + 8);
        }
        asm volatile("cp.async.commit_group;" ::: "memory");
    };

    load_stage(0);
    load_stage(1);

    for (int s = 0; s < S; s++) {
        if (s + 1 < S) { asm volatile("cp.async.wait_group 1;" ::: "memory"); }
        else           { asm volatile("cp.async.wait_group 0;" ::: "memory"); }
        __syncthreads();
        if (s + 2 < S) load_stage(s + 2);

        const __half* bufA = sAb + (s % 3) * STAGE_H;
        const __half* bufB = sBb + (s % 3) * STAGE_H;
        #pragma unroll
        for (int ks = 0; ks < 2; ks++) {
            uint32_t a[2][4], b[8][2];
            #pragma unroll
            for (int mt = 0; mt < 2; mt++) {
                int row = wm * 32 + mt * 16 + (lane & 15);
                uint32_t ad = smem_u32(bufA + row * RS + ks * 16 + (lane >> 4) * 8);
                ldmx4(ad, a[mt][0], a[mt][1], a[mt][2], a[mt][3]);
            }
            #pragma unroll
            for (int q = 0; q < 4; q++) {
                int nr = wn * 64 + q * 16 + (lane >> 4) * 8 + (lane & 7);
                uint32_t bd = smem_u32(bufB + nr * RS + ks * 16 + ((lane >> 3) & 1) * 8);
                ldmx4(bd, b[2 * q][0], b[2 * q][1], b[2 * q + 1][0], b[2 * q + 1][1]);
            }
            #pragma unroll
            for (int mt = 0; mt < 2; mt++)
                #pragma unroll
                for (int nt = 0; nt < 8; nt++)
                    mma16816(acc[mt][nt], a[mt], b[nt]);
        }
    }

    float* Pb = Pp + n0;
    #pragma unroll
    for (int mt = 0; mt < 2; mt++) {
        int r = wm * 32 + mt * 16 + (lane >> 2);
        #pragma unroll
        for (int nt = 0; nt < 8; nt++) {
            int cc = wn * 64 + nt * 8 + (lane & 3) * 2;
            *(float2*)(Pb + (size_t)r * NFULL + cc)       = make_float2(acc[mt][nt][0], acc[mt][nt][1]);
            *(float2*)(Pb + (size_t)(r + 8) * NFULL + cc) = make_float2(acc[mt][nt][2], acc[mt][nt][3]);
        }
    }
}

template <int KLOC, int NFULL>
__global__ void __launch_bounds__(256) gemm_mma(const __half* __restrict__ A,
                                                const __half* __restrict__ B,
                                                float* __restrict__ P)
{
    extern __shared__ __align__(128) __half dynsm[];
    gemm_body<KLOC, NFULL>(A, B, P + (size_t)blockIdx.y * BATCH * NFULL,
                           blockIdx.x * 128, blockIdx.y * KLOC, dynsm, dynsm + 3 * STAGE_H);
}

// ---------------- elementwise helpers ----------------
__device__ __forceinline__ void f4_add(float4& a, const float4 b) {
    a.x += b.x; a.y += b.y; a.z += b.z; a.w += b.w;
}
__device__ __forceinline__ float4 f4_axpy(float al, const float4 a, const float4 b) {
    return make_float4(fmaf(al, a.x, b.x), fmaf(al, a.y, b.y), fmaf(al, a.z, b.z), fmaf(al, a.w, b.w));
}
__device__ __forceinline__ void lif_spike_reset(float4& m, float4& spk) {
    bool fx = (m.x - 1.0f) > 0.0f, fy = (m.y - 1.0f) > 0.0f;
    bool fz = (m.z - 1.0f) > 0.0f, fw = (m.w - 1.0f) > 0.0f;
    spk.x = fx ? 1.0f : 0.0f; if (fx) m.x = 0.0f;
    spk.y = fy ? 1.0f : 0.0f; if (fy) m.y = 0.0f;
    spk.z = fz ? 1.0f : 0.0f; if (fz) m.z = 0.0f;
    spk.w = fw ? 1.0f : 0.0f; if (fw) m.w = 0.0f;
}
__device__ __forceinline__ void store_spk_h(__half* base, int idx, const float4 spk) {
    __half2 p0 = __floats2half2_rn(spk.x, spk.y);
    __half2 p1 = __floats2half2_rn(spk.z, spk.w);
    unsigned long long v = (unsigned long long)(*(unsigned*)&p0)
                         | ((unsigned long long)(*(unsigned*)&p1) << 32);
    ((unsigned long long*)base)[idx] = v;
}

// ---------------- persistent loop kernel ----------------
__global__ void __launch_bounds__(256, 1) persistent_loop(float* __restrict__ out)
{
    extern __shared__ __align__(128) __half dynsm[];
    __half* sW1 = dynsm + SW1_OFF;
    __half* sW2 = dynsm + SW2_OFF;
    __half* sA  = dynsm + SA_OFF;
    const int cta = blockIdx.x;
    const int tid = threadIdx.x;
    unsigned gen = 0;

    const int n0_1 = (cta & 15) * 128, kb_1 = (cta >> 4) * 512;   // GEMM1: 16 N x 8 K
    const int n0_2 = (cta & 7) * 64,   kb_2 = (cta >> 3) * 256;   // GEMM2: 8 N x 16 K
    const int ka_1 = kb_1 & (KS - 1);
    const int ka_2 = kb_2 & (KS - 1);

    // ---- load resident weight tiles once ----
    for (int c = tid; c < 8192; c += 256) {            // W1: 128 rows x 64 chunks
        int r = c >> 6, j = c & 63;
        cp16(smem_u32(sW1 + r * W1_RS + j * 8), g_W1Th + (size_t)(n0_1 + r) * KF + kb_1 + j * 8);
    }
    for (int c = tid; c < 2048; c += 256) {            // W2: 64 rows x 32 chunks
        int r = c >> 5, j = c & 31;
        cp16(smem_u32(sW2 + r * W2_RS + j * 8), g_W2Th + (size_t)(n0_2 + r) * KF + kb_2 + j * 8);
    }
    asm volatile("cp.async.commit_group;" ::: "memory");
    asm volatile("cp.async.wait_group 0;" ::: "memory");
    __syncthreads();

    // ---- preamble (was reduce0): H0 = sum of 8 partials; step-0 layer0 ----
    #pragma unroll
    for (int r = 0; r < 2; r++) {
        int idx = cta * 512 + r * 256 + tid;           // f4 over [128][2048]
        float4 h = make_float4(0.f, 0.f, 0.f, 0.f);
        #pragma unroll
        for (int ks = 0; ks < 8; ks++) f4_add(h, ((const float4*)g_p1)[(size_t)ks * 65536 + idx]);
        ((float4*)g_H0)[idx] = h;
        float4 m = h, spk;
        lif_spike_reset(m, spk);
        ((float4*)g_m0)[idx] = m;
        store_spk_h(g_spk0h[0], idx, spk);
    }
    gridbar(++gen * NCTA);

    for (int t = 0; t < TSTEPS; t++) {
        // ---- phase X: GEMM1(t) [A prestaged for t>0] + GEMM2(t-1) + l0 update(t+1) ----
        gemm_res128<8, W1_RS, 2048>(g_spk0h[t & 1] + ka_1, sW1, sA,
                                    g_p1 + (size_t)(cta >> 4) * BATCH * 2048, n0_1,
                                    t > 0 ? 2 : 0);
        if (t > 0)
            gemm_res64<4, W2_RS, 512>(g_spk1h + ka_2, sW2, sA,
                                      g_p2 + (size_t)(cta >> 3) * BATCH * 512, n0_2);
        if (t + 1 < TSTEPS) {
            __half* spknext = g_spk0h[(t + 1) & 1];
            #pragma unroll
            for (int r = 0; r < 2; r++) {
                int idx = cta * 512 + r * 256 + tid;
                float4 m = f4_axpy(BETA_C, ((float4*)g_m0)[idx], ((float4*)g_H0)[idx]);
                float4 spk;
                lif_spike_reset(m, spk);
                ((float4*)g_m0)[idx] = m;
                store_spk_h(spknext, idx, spk);
            }
        }
        gridbar(++gen * NCTA);

        // ---- phase Y: preload GEMM1(t+1) A stages ; lif1(t) ; lif2(t-1) ----
        if (t + 1 < TSTEPS) {
            const __half* An = g_spk0h[(t + 1) & 1] + ka_1;   // sealed at X(t) barrier
            stage_A(An, sA, 0);
            stage_A(An, sA, 1);
        }
        #pragma unroll
        for (int r = 0; r < 2; r++) {
            int idx = cta * 512 + r * 256 + tid;
            float4 h = make_float4(0.f, 0.f, 0.f, 0.f);
            #pragma unroll
            for (int ks = 0; ks < 8; ks++) f4_add(h, ((const float4*)g_p1)[(size_t)ks * 65536 + idx]);
            float4 s = f4_axpy(ALPHA_C, ((float4*)g_s1)[idx], h);
            float4 m = f4_axpy(BETA_C, ((float4*)g_m1)[idx], s);
            float4 spk;
            lif_spike_reset(m, spk);
            ((float4*)g_s1)[idx] = s;
            ((float4*)g_m1)[idx] = m;
            store_spk_h(g_spk1h, idx, spk);
        }
        if (t > 0 && tid < 128) {
            int idx = cta * 128 + tid;                         // f4 over [128][512]
            float4 h = make_float4(0.f, 0.f, 0.f, 0.f);
            #pragma unroll
            for (int ks = 0; ks < 16; ks++) f4_add(h, ((const float4*)g_p2)[(size_t)ks * 16384 + idx]);
            float4 s = f4_axpy(ALPHA_C, ((float4*)g_s2)[idx], h);
            float4 m = f4_axpy(BETA_C, ((float4*)g_m2)[idx], s);   // output layer: no reset
            ((float4*)g_s2)[idx] = s;
            ((float4*)g_m2)[idx] = m;
        }
        gridbar(++gen * NCTA);
    }

    // ---- tail: GEMM2(T-1), then final lif2 + output ----
    gemm_res64<4, W2_RS, 512>(g_spk1h + ka_2, sW2, sA,
                              g_p2 + (size_t)(cta >> 3) * BATCH * 512, n0_2);
    gridbar(++gen * NCTA);

    if (tid < 128) {
        int idx = cta * 128 + tid;
        float4 h = make_float4(0.f, 0.f, 0.f, 0.f);
        #pragma unroll
        for (int ks = 0; ks < 16; ks++) f4_add(h, ((const float4*)g_p2)[(size_t)ks * 16384 + idx]);
        float4 s = f4_axpy(ALPHA_C, ((float4*)g_s2)[idx], h);
        float4 m = f4_axpy(BETA_C, ((float4*)g_m2)[idx], s);
        ((float4*)out)[idx] = m;
    }
}

// ---------------- one-time prep kernels ----------------
// fused: state zeroing + barrier reset + input hi/lo split
__global__ void prep1(const float* __restrict__ inp)
{
    int g = blockIdx.x * blockDim.x + threadIdx.x;     // < 131072
    int m = g >> 10, k = g & 1023;
    float v = inp[g];
    __half hi = __float2half_rn(v);
    __half lo = __float2half_rn(v - __half2float(hi));
    size_t row = (size_t)m * KF;
    g_inh[row + k] = hi;
    g_inh[row + 1024 + k] = lo;
    g_inh[row + 2048 + k] = hi;
    g_inh[row + 3072 + k] = __float2half_rn(0.f);

    float4 z = make_float4(0.f, 0.f, 0.f, 0.f);
    if (g < 65536) { ((float4*)g_s1)[g] = z; ((float4*)g_m1)[g] = z; }
    if (g < 16384) { ((float4*)g_s2)[g] = z; ((float4*)g_m2)[g] = z; }
    if (g == 0) g_ctr = 0u;
}

__global__ void conv_w(const float* __restrict__ W, __half* __restrict__ WT, int N)
{
    __shared__ float t[32][33];
    const int k0 = blockIdx.x * 32, nb = blockIdx.y * 32;
    const int tx = threadIdx.x, ty = threadIdx.y;
    for (int i = ty; i < 32; i += 8)
        t[i][tx] = W[(size_t)(k0 + i) * N + nb + tx];
    __syncthreads();
    if (tx < 16) {
        for (int n2 = ty; n2 < 32; n2 += 8) {
            float w0 = t[2 * tx][n2], w1 = t[2 * tx + 1][n2];
            __half h0 = __float2half_rn(w0), h1 = __float2half_rn(w1);
            __half l0 = __float2half_rn(w0 - __half2float(h0));
            __half l1 = __float2half_rn(w1 - __half2float(h1));
            size_t row = (size_t)(nb + n2) * KF;
            ((__half2*)(WT + row + k0))[tx]        = __halves2half2(h0, h1);
            ((__half2*)(WT + row + 2048 + k0))[tx] = __halves2half2(l0, l1);
        }
    }
}

__global__ void conv_w0(const float* __restrict__ W, __half* __restrict__ WT)
{
    __shared__ float t[32][33];
    const int k0 = blockIdx.x * 32, nb = blockIdx.y * 32;
    const int tx = threadIdx.x, ty = threadIdx.y;
    for (int i = ty; i < 32; i += 8)
        t[i][tx] = W[(size_t)(k0 + i) * 2048 + nb + tx];
    __syncthreads();
    if (tx < 16) {
        for (int n2 = ty; n2 < 32; n2 += 8) {
            float w0 = t[2 * tx][n2], w1 = t[2 * tx + 1][n2];
            __half h0 = __float2half_rn(w0), h1 = __float2half_rn(w1);
            __half l0 = __float2half_rn(w0 - __half2float(h0));
            __half l1 = __float2half_rn(w1 - __half2float(h1));
            size_t row = (size_t)(nb + n2) * KF;
            __half2 hh = __halves2half2(h0, h1);
            ((__half2*)(WT + row + k0))[tx]        = hh;                        // seg0: hi
            ((__half2*)(WT + row + 1024 + k0))[tx] = hh;                        // seg1: hi
            ((__half2*)(WT + row + 2048 + k0))[tx] = __halves2half2(l0, l1);    // seg2: lo
            ((__half2*)(WT + row + 3072 + k0))[tx] = __halves2half2(__float2half_rn(0.f), __float2half_rn(0.f));
        }
    }
}

// ---------------- launch ----------------
extern "C" void kernel_launch(void* const* d_in, const int* in_sizes, int n_in,
                              void* d_out, int out_size)
{
    const float* inp = nullptr; const float* W0 = nullptr;
    const float* W1 = nullptr;  const float* W2 = nullptr;
    for (int i = 0; i < n_in; i++) {
        switch (in_sizes[i]) {
            case BATCH * K0: inp = (const float*)d_in[i]; break;
            case K0 * N0:    W0  = (const float*)d_in[i]; break;
            case 2048 * N1:  W1  = (const float*)d_in[i]; break;
            case 2048 * N2:  W2  = (const float*)d_in[i]; break;
        }
    }

    float* p1;
    __half *inh, *w0t, *w1t, *w2t;
    cudaGetSymbolAddress((void**)&p1,  g_p1);
    cudaGetSymbolAddress((void**)&inh, g_inh);
    cudaGetSymbolAddress((void**)&w0t, g_W0Th);
    cudaGetSymbolAddress((void**)&w1t, g_W1Th);
    cudaGetSymbolAddress((void**)&w2t, g_W2Th);

    static bool attr_done = false;
    if (!attr_done) {
        cudaFuncSetAttribute(gemm_mma<512, 2048>, cudaFuncAttributeMaxDynamicSharedMemorySize, H0_SMEM_BYTES);
        cudaFuncSetAttribute(persistent_loop, cudaFuncAttributeMaxDynamicSharedMemorySize, PERS_SMEM_BYTES);
        attr_done = true;
    }

    // launch order fixed at 6 so ncu (-s 5 -c 1) captures persistent_loop
    prep1<<<512, 256>>>(inp);                                       // #1
    conv_w0<<<dim3(32, 64), dim3(32, 8)>>>(W0, w0t);                // #2
    conv_w<<<dim3(64, 64), dim3(32, 8)>>>(W1, w1t, N1);             // #3
    conv_w<<<dim3(64, 16), dim3(32, 8)>>>(W2, w2t, N2);             // #4
    gemm_mma<512, 2048><<<dim3(16, 8), 256, H0_SMEM_BYTES>>>(inh, w0t, p1);  // #5
    persistent_loop<<<NCTA, 256, PERS_SMEM_BYTES>>>((float*)d_out); // #6
}

// round 15
// speedup vs baseline: 3.8466x; 1.0079x over previous
#include <cuda_runtime.h>
#include <cuda_fp16.h>
#include <cstdint>

#define BATCH 128
#define N0 2048
#define N1 2048
#define N2 512
#define K0 1024
#define KF 4096            // hi|lo concatenated K dimension (weights)
#define KS 2048            // spike storage stride
#define ALPHA_C 0.9f
#define BETA_C  0.85f
#define TSTEPS 50
#define NCTA 128

// ---- H0 standalone GEMM staging ----
#define RS 40
#define STAGE_H (128 * RS)
#define H0_SMEM_BYTES (3 * STAGE_H * 2 * 2)      // 61440

// ---- persistent kernel smem layout (halves) ----
#define W1_RS 520                                 // 512 + 8 pad (128-wide tile, K_loc 512)
#define W2_RS 264                                 // 256 + 8 pad (64-wide tile, K_loc 256)
#define A_RS  72                                  // 64 + 8 pad
#define A_STG (128 * A_RS)                        // 9216 halves / stage
#define SW1_OFF 0
#define SW2_OFF (128 * W1_RS)                     // 66560
#define SA_OFF  (SW2_OFF + 64 * W2_RS)            // 83456
#define PERS_SMEM_BYTES ((SA_OFF + 3 * A_STG) * 2)  // 222208 B

// ---------------- static device scratch ----------------
__device__ float g_H0[BATCH * N0];
__device__ float g_m0[BATCH * N0];
__device__ float g_s1[BATCH * N1];
__device__ float g_m1[BATCH * N1];
__device__ float g_s2[BATCH * N2];
__device__ float g_m2[BATCH * N2];
__device__ __half g_spk0h[2][BATCH * KS];  // layer0 spikes fp16, double-buffered
__device__ __half g_spk1h[BATCH * KS];     // layer1 spikes fp16
__device__ __half g_inh[BATCH * KF];       // input ext: [hi | lo | hi | 0]
__device__ __half g_W0Th[N0 * KF];         // [n][k]: [hiW | hiW | loW | 0]
__device__ __half g_W1Th[N1 * KF];         // [n][k]: k<2048 hi, k>=2048 lo
__device__ __half g_W2Th[N2 * KF];
__device__ float g_p1[8 * BATCH * N1];     // split-K partials (H0 GEMM 8 / GEMM1 8)
__device__ float g_p2[16 * BATCH * N2];    // split-K partials GEMM2 (16)
__device__ unsigned g_ctr;                 // grid barrier counter

// ---------------- PTX helpers ----------------
__device__ __forceinline__ uint32_t smem_u32(const void* p) {
    uint32_t a;
    asm("{ .reg .u64 t; cvta.to.shared.u64 t, %1; cvt.u32.u64 %0, t; }" : "=r"(a) : "l"(p));
    return a;
}
__device__ __forceinline__ void cp16(uint32_t dst, const void* src) {
    asm volatile("cp.async.cg.shared.global [%0], [%1], 16;" :: "r"(dst), "l"(src));
}
__device__ __forceinline__ void ldmx4(uint32_t addr, uint32_t& r0, uint32_t& r1,
                                      uint32_t& r2, uint32_t& r3) {
    asm volatile("ldmatrix.sync.aligned.m8n8.x4.shared.b16 {%0,%1,%2,%3}, [%4];"
                 : "=r"(r0), "=r"(r1), "=r"(r2), "=r"(r3) : "r"(addr));
}
__device__ __forceinline__ void mma16816(float* d, const uint32_t* a, const uint32_t* b) {
    asm volatile(
        "mma.sync.aligned.m16n8k16.row.col.f32.f16.f16.f32 "
        "{%0,%1,%2,%3}, {%4,%5,%6,%7}, {%8,%9}, {%0,%1,%2,%3};"
        : "+f"(d[0]), "+f"(d[1]), "+f"(d[2]), "+f"(d[3])
        : "r"(a[0]), "r"(a[1]), "r"(a[2]), "r"(a[3]), "r"(b[0]), "r"(b[1]));
}
__device__ __forceinline__ unsigned ld_acq(const unsigned* p) {
    unsigned v;
    asm volatile("ld.global.acquire.gpu.u32 %0, [%1];" : "=r"(v) : "l"(p) : "memory");
    return v;
}
__device__ __forceinline__ void red_rel_add(unsigned* p, unsigned v) {
    asm volatile("red.release.gpu.global.add.u32 [%0], %1;" :: "l"(p), "r"(v) : "memory");
}

// ---------------- grid-wide barrier ----------------
__device__ __forceinline__ void gridbar(unsigned target) {
    __syncthreads();
    if (threadIdx.x == 0) {
        red_rel_add(&g_ctr, 1u);
        while (ld_acq(&g_ctr) < target) { }
    }
    __syncthreads();
}

// ---------------- A-stage loader (128 rows x 64 k, triple-buffered ring) ----------------
__device__ __forceinline__ void stage_A(const __half* __restrict__ A, __half* __restrict__ sA, int s) {
    const int tid = threadIdx.x;
    const int buf = s % 3;
    const int k0 = s * 64;
    __half* d = sA + buf * A_STG;
    #pragma unroll
    for (int i = 0; i < 4; i++) {
        int c = tid + i * 256;                 // 1024 16B chunks
        int r = c >> 3, j = c & 7;
        cp16(smem_u32(d + r * A_RS + j * 8), A + (size_t)r * KS + k0 + j * 8);
    }
    asm volatile("cp.async.commit_group;" ::: "memory");
}

// ---------------- resident-weight HMMA GEMM: 128x128 tile ----------------
// nextA2 (if non-null): after the mainloop drains the ring, prestage that
// operand's stage 0/1 so the following gemm_res64 starts hot.
template <int S, int BRS, int NFULL>
__device__ __forceinline__ void gemm_res128(const __half* __restrict__ A,
                                            const __half* __restrict__ sB,
                                            __half* __restrict__ sA,
                                            float* __restrict__ Pp,
                                            int n0, int preloaded,
                                            const __half* __restrict__ nextA2)
{
    const int tid = threadIdx.x, lane = tid & 31, wid = tid >> 5;
    const int wm = wid & 3, wn = wid >> 2;

    float acc[2][8][4];
    #pragma unroll
    for (int mt = 0; mt < 2; mt++)
        #pragma unroll
        for (int nt = 0; nt < 8; nt++)
            #pragma unroll
            for (int q = 0; q < 4; q++) acc[mt][nt][q] = 0.f;

    if (preloaded < 1) stage_A(A, sA, 0);
    if (S > 1 && preloaded < 2) stage_A(A, sA, 1);

    for (int s = 0; s < S; s++) {
        if (s + 1 < S) { asm volatile("cp.async.wait_group 1;" ::: "memory"); }
        else           { asm volatile("cp.async.wait_group 0;" ::: "memory"); }
        __syncthreads();
        if (s + 2 < S) stage_A(A, sA, s + 2);

        const __half* bufA = sA + (s % 3) * A_STG;
        #pragma unroll
        for (int ks = 0; ks < 4; ks++) {
            uint32_t a[2][4], b[8][2];
            #pragma unroll
            for (int mt = 0; mt < 2; mt++) {
                int row = wm * 32 + mt * 16 + (lane & 15);
                uint32_t ad = smem_u32(bufA + row * A_RS + ks * 16 + (lane >> 4) * 8);
                ldmx4(ad, a[mt][0], a[mt][1], a[mt][2], a[mt][3]);
            }
            #pragma unroll
            for (int q = 0; q < 4; q++) {
                int nr = wn * 64 + q * 16 + (lane >> 4) * 8 + (lane & 7);
                uint32_t bd = smem_u32(sB + nr * BRS + s * 64 + ks * 16 + ((lane >> 3) & 1) * 8);
                ldmx4(bd, b[2 * q][0], b[2 * q][1], b[2 * q + 1][0], b[2 * q + 1][1]);
            }
            #pragma unroll
            for (int mt = 0; mt < 2; mt++)
                #pragma unroll
                for (int nt = 0; nt < 8; nt++)
                    mma16816(acc[mt][nt], a[mt], b[nt]);
        }
    }
    __syncthreads();          // ring fully consumed

    if (nextA2) {             // prestage the next GEMM's A under our epilogue
        stage_A(nextA2, sA, 0);
        stage_A(nextA2, sA, 1);
    }

    float* Pb = Pp + n0;
    #pragma unroll
    for (int mt = 0; mt < 2; mt++) {
        int r = wm * 32 + mt * 16 + (lane >> 2);
        #pragma unroll
        for (int nt = 0; nt < 8; nt++) {
            int cc = wn * 64 + nt * 8 + (lane & 3) * 2;
            *(float2*)(Pb + (size_t)r * NFULL + cc)       = make_float2(acc[mt][nt][0], acc[mt][nt][1]);
            *(float2*)(Pb + (size_t)(r + 8) * NFULL + cc) = make_float2(acc[mt][nt][2], acc[mt][nt][3]);
        }
    }
}

// ---------------- resident-weight HMMA GEMM: 128x64 tile (GEMM2) ----------------
template <int S, int BRS, int NFULL>
__device__ __forceinline__ void gemm_res64(const __half* __restrict__ A,
                                           const __half* __restrict__ sB,
                                           __half* __restrict__ sA,
                                           float* __restrict__ Pp,
                                           int n0, int preloaded)
{
    const int tid = threadIdx.x, lane = tid & 31, wid = tid >> 5;
    const int wm = wid & 3, wn = wid >> 2;          // wn in {0,1}: 32-col halves

    float acc[2][4][4];
    #pragma unroll
    for (int mt = 0; mt < 2; mt++)
        #pragma unroll
        for (int nt = 0; nt < 4; nt++)
            #pragma unroll
            for (int q = 0; q < 4; q++) acc[mt][nt][q] = 0.f;

    if (preloaded < 1) stage_A(A, sA, 0);
    if (S > 1 && preloaded < 2) stage_A(A, sA, 1);

    for (int s = 0; s < S; s++) {
        if (s + 1 < S) { asm volatile("cp.async.wait_group 1;" ::: "memory"); }
        else           { asm volatile("cp.async.wait_group 0;" ::: "memory"); }
        __syncthreads();
        if (s + 2 < S) stage_A(A, sA, s + 2);

        const __half* bufA = sA + (s % 3) * A_STG;
        #pragma unroll
        for (int ks = 0; ks < 4; ks++) {
            uint32_t a[2][4], b[4][2];
            #pragma unroll
            for (int mt = 0; mt < 2; mt++) {
                int row = wm * 32 + mt * 16 + (lane & 15);
                uint32_t ad = smem_u32(bufA + row * A_RS + ks * 16 + (lane >> 4) * 8);
                ldmx4(ad, a[mt][0], a[mt][1], a[mt][2], a[mt][3]);
            }
            #pragma unroll
            for (int q = 0; q < 2; q++) {
                int nr = wn * 32 + q * 16 + (lane >> 4) * 8 + (lane & 7);
                uint32_t bd = smem_u32(sB + nr * BRS + s * 64 + ks * 16 + ((lane >> 3) & 1) * 8);
                ldmx4(bd, b[2 * q][0], b[2 * q][1], b[2 * q + 1][0], b[2 * q + 1][1]);
            }
            #pragma unroll
            for (int mt = 0; mt < 2; mt++)
                #pragma unroll
                for (int nt = 0; nt < 4; nt++)
                    mma16816(acc[mt][nt], a[mt], b[nt]);
        }
    }
    __syncthreads();

    float* Pb = Pp + n0;
    #pragma unroll
    for (int mt = 0; mt < 2; mt++) {
        int r = wm * 32 + mt * 16 + (lane >> 2);
        #pragma unroll
        for (int nt = 0; nt < 4; nt++) {
            int cc = wn * 32 + nt * 8 + (lane & 3) * 2;
            *(float2*)(Pb + (size_t)r * NFULL + cc)       = make_float2(acc[mt][nt][0], acc[mt][nt][1]);
            *(float2*)(Pb + (size_t)(r + 8) * NFULL + cc) = make_float2(acc[mt][nt][2], acc[mt][nt][3]);
        }
    }
}

// ---------------- fully-staged GEMM body (used once for H0, KF strides) ----------------
template <int KLOC, int NFULL>
__device__ __forceinline__ void gemm_body(const __half* __restrict__ A,
                                          const __half* __restrict__ B,
                                          float* __restrict__ Pp,
                                          int n0, int kbase,
                                          __half* sAb, __half* sBb)
{
    constexpr int S = KLOC / 32;
    const int tid = threadIdx.x, lane = tid & 31, wid = tid >> 5;
    const int wm = wid & 3, wn = wid >> 2;

    float acc[2][8][4];
    #pragma unroll
    for (int mt = 0; mt < 2; mt++)
        #pragma unroll
        for (int nt = 0; nt < 8; nt++)
            #pragma unroll
            for (int q = 0; q < 4; q++) acc[mt][nt][q] = 0.f;

    auto load_stage = [&](int s) {
        const int buf = s % 3;
        const int k0 = kbase + s * 32;
        __half* dA = sAb + buf * STAGE_H;
        __half* dB = sBb + buf * STAGE_H;
        {
            int r = tid >> 1, sub = (tid & 1) * 2;
            cp16(smem_u32(dA + r * RS + sub * 8),     A + (size_t)r * KF + k0 + sub * 8);
            cp16(smem_u32(dA + r * RS + sub * 8 + 8), A + (size_t)r * KF + k0 + sub * 8 + 8);
            cp16(smem_u32(dB + r * RS + sub * 8),     B + (size_t)(n0 + r) * KF + k0 + sub * 8);
            cp16(smem_u32(dB + r * RS + sub * 8 + 8), B + (size_t)(n0 + r) * KF + k0 + sub * 8 + 8);
        }
        asm volatile("cp.async.commit_group;" ::: "memory");
    };

    load_stage(0);
    load_stage(1);

    for (int s = 0; s < S; s++) {
        if (s + 1 < S) { asm volatile("cp.async.wait_group 1;" ::: "memory"); }
        else           { asm volatile("cp.async.wait_group 0;" ::: "memory"); }
        __syncthreads();
        if (s + 2 < S) load_stage(s + 2);

        const __half* bufA = sAb + (s % 3) * STAGE_H;
        const __half* bufB = sBb + (s % 3) * STAGE_H;
        #pragma unroll
        for (int ks = 0; ks < 2; ks++) {
            uint32_t a[2][4], b[8][2];
            #pragma unroll
            for (int mt = 0; mt < 2; mt++) {
                int row = wm * 32 + mt * 16 + (lane & 15);
                uint32_t ad = smem_u32(bufA + row * RS + ks * 16 + (lane >> 4) * 8);
                ldmx4(ad, a[mt][0], a[mt][1], a[mt][2], a[mt][3]);
            }
            #pragma unroll
            for (int q = 0; q < 4; q++) {
                int nr = wn * 64 + q * 16 + (lane >> 4) * 8 + (lane & 7);
                uint32_t bd = smem_u32(bufB + nr * RS + ks * 16 + ((lane >> 3) & 1) * 8);
                ldmx4(bd, b[2 * q][0], b[2 * q][1], b[2 * q + 1][0], b[2 * q + 1][1]);
            }
            #pragma unroll
            for (int mt = 0; mt < 2; mt++)
                #pragma unroll
                for (int nt = 0; nt < 8; nt++)
                    mma16816(acc[mt][nt], a[mt], b[nt]);
        }
    }

    float* Pb = Pp + n0;
    #pragma unroll
    for (int mt = 0; mt < 2; mt++) {
        int r = wm * 32 + mt * 16 + (lane >> 2);
        #pragma unroll
        for (int nt = 0; nt < 8; nt++) {
            int cc = wn * 64 + nt * 8 + (lane & 3) * 2;
            *(float2*)(Pb + (size_t)r * NFULL + cc)       = make_float2(acc[mt][nt][0], acc[mt][nt][1]);
            *(float2*)(Pb + (size_t)(r + 8) * NFULL + cc) = make_float2(acc[mt][nt][2], acc[mt][nt][3]);
        }
    }
}

template <int KLOC, int NFULL>
__global__ void __launch_bounds__(256) gemm_mma(const __half* __restrict__ A,
                                                const __half* __restrict__ B,
                                                float* __restrict__ P)
{
    extern __shared__ __align__(128) __half dynsm[];
    gemm_body<KLOC, NFULL>(A, B, P + (size_t)blockIdx.y * BATCH * NFULL,
                           blockIdx.x * 128, blockIdx.y * KLOC, dynsm, dynsm + 3 * STAGE_H);
}

// ---------------- elementwise helpers ----------------
__device__ __forceinline__ void f4_add(float4& a, const float4 b) {
    a.x += b.x; a.y += b.y; a.z += b.z; a.w += b.w;
}
__device__ __forceinline__ float4 f4_axpy(float al, const float4 a, const float4 b) {
    return make_float4(fmaf(al, a.x, b.x), fmaf(al, a.y, b.y), fmaf(al, a.z, b.z), fmaf(al, a.w, b.w));
}
__device__ __forceinline__ void lif_spike_reset(float4& m, float4& spk) {
    bool fx = (m.x - 1.0f) > 0.0f, fy = (m.y - 1.0f) > 0.0f;
    bool fz = (m.z - 1.0f) > 0.0f, fw = (m.w - 1.0f) > 0.0f;
    spk.x = fx ? 1.0f : 0.0f; if (fx) m.x = 0.0f;
    spk.y = fy ? 1.0f : 0.0f; if (fy) m.y = 0.0f;
    spk.z = fz ? 1.0f : 0.0f; if (fz) m.z = 0.0f;
    spk.w = fw ? 1.0f : 0.0f; if (fw) m.w = 0.0f;
}
__device__ __forceinline__ void store_spk_h(__half* base, int idx, const float4 spk) {
    __half2 p0 = __floats2half2_rn(spk.x, spk.y);
    __half2 p1 = __floats2half2_rn(spk.z, spk.w);
    unsigned long long v = (unsigned long long)(*(unsigned*)&p0)
                         | ((unsigned long long)(*(unsigned*)&p1) << 32);
    ((unsigned long long*)base)[idx] = v;
}

// ---------------- persistent loop kernel ----------------
__global__ void __launch_bounds__(256, 1) persistent_loop(float* __restrict__ out)
{
    extern __shared__ __align__(128) __half dynsm[];
    __half* sW1 = dynsm + SW1_OFF;
    __half* sW2 = dynsm + SW2_OFF;
    __half* sA  = dynsm + SA_OFF;
    const int cta = blockIdx.x;
    const int tid = threadIdx.x;
    unsigned gen = 0;

    const int n0_1 = (cta & 15) * 128, kb_1 = (cta >> 4) * 512;   // GEMM1: 16 N x 8 K
    const int n0_2 = (cta & 7) * 64,   kb_2 = (cta >> 3) * 256;   // GEMM2: 8 N x 16 K
    const int ka_1 = kb_1 & (KS - 1);
    const int ka_2 = kb_2 & (KS - 1);

    // ---- load resident weight tiles once ----
    for (int c = tid; c < 8192; c += 256) {            // W1: 128 rows x 64 chunks
        int r = c >> 6, j = c & 63;
        cp16(smem_u32(sW1 + r * W1_RS + j * 8), g_W1Th + (size_t)(n0_1 + r) * KF + kb_1 + j * 8);
    }
    for (int c = tid; c < 2048; c += 256) {            // W2: 64 rows x 32 chunks
        int r = c >> 5, j = c & 31;
        cp16(smem_u32(sW2 + r * W2_RS + j * 8), g_W2Th + (size_t)(n0_2 + r) * KF + kb_2 + j * 8);
    }
    asm volatile("cp.async.commit_group;" ::: "memory");
    asm volatile("cp.async.wait_group 0;" ::: "memory");
    __syncthreads();

    // ---- preamble: H0 = sum of 8 partials; step-0 layer0 ----
    #pragma unroll
    for (int r = 0; r < 2; r++) {
        int idx = cta * 512 + r * 256 + tid;           // f4 over [128][2048]
        float4 h = make_float4(0.f, 0.f, 0.f, 0.f);
        #pragma unroll
        for (int ks = 0; ks < 8; ks++) f4_add(h, ((const float4*)g_p1)[(size_t)ks * 65536 + idx]);
        ((float4*)g_H0)[idx] = h;
        float4 m = h, spk;
        lif_spike_reset(m, spk);
        ((float4*)g_m0)[idx] = m;
        store_spk_h(g_spk0h[0], idx, spk);
    }
    gridbar(++gen * NCTA);

    for (int t = 0; t < TSTEPS; t++) {
        // ---- phase X: GEMM1(t) [A prestaged for t>0; prestages GEMM2 A] +
        //              GEMM2(t-1) [hot] + l0 update(t+1) ----
        gemm_res128<8, W1_RS, 2048>(g_spk0h[t & 1] + ka_1, sW1, sA,
                                    g_p1 + (size_t)(cta >> 4) * BATCH * 2048, n0_1,
                                    t > 0 ? 2 : 0,
                                    t > 0 ? g_spk1h + ka_2 : (const __half*)nullptr);
        if (t > 0)
            gemm_res64<4, W2_RS, 512>(g_spk1h + ka_2, sW2, sA,
                                      g_p2 + (size_t)(cta >> 3) * BATCH * 512, n0_2, 2);
        if (t + 1 < TSTEPS) {
            __half* spknext = g_spk0h[(t + 1) & 1];
            #pragma unroll
            for (int r = 0; r < 2; r++) {
                int idx = cta * 512 + r * 256 + tid;
                float4 m = f4_axpy(BETA_C, ((float4*)g_m0)[idx], ((float4*)g_H0)[idx]);
                float4 spk;
                lif_spike_reset(m, spk);
                ((float4*)g_m0)[idx] = m;
                store_spk_h(spknext, idx, spk);
            }
        }
        gridbar(++gen * NCTA);

        // ---- phase Y: preload GEMM1(t+1) A stages ; lif1(t) ; lif2(t-1) ----
        if (t + 1 < TSTEPS) {
            const __half* An = g_spk0h[(t + 1) & 1] + ka_1;   // sealed at X(t) barrier
            stage_A(An, sA, 0);
            stage_A(An, sA, 1);
        }
        #pragma unroll
        for (int r = 0; r < 2; r++) {
            int idx = cta * 512 + r * 256 + tid;
            float4 h = make_float4(0.f, 0.f, 0.f, 0.f);
            #pragma unroll
            for (int ks = 0; ks < 8; ks++) f4_add(h, ((const float4*)g_p1)[(size_t)ks * 65536 + idx]);
            float4 s = f4_axpy(ALPHA_C, ((float4*)g_s1)[idx], h);
            float4 m = f4_axpy(BETA_C, ((float4*)g_m1)[idx], s);
            float4 spk;
            lif_spike_reset(m, spk);
            ((float4*)g_s1)[idx] = s;
            ((float4*)g_m1)[idx] = m;
            store_spk_h(g_spk1h, idx, spk);
        }
        if (t > 0 && tid < 128) {
            int idx = cta * 128 + tid;                         // f4 over [128][512]
            float4 h = make_float4(0.f, 0.f, 0.f, 0.f);
            #pragma unroll
            for (int ks = 0; ks < 16; ks++) f4_add(h, ((const float4*)g_p2)[(size_t)ks * 16384 + idx]);
            float4 s = f4_axpy(ALPHA_C, ((float4*)g_s2)[idx], h);
            float4 m = f4_axpy(BETA_C, ((float4*)g_m2)[idx], s);   // output layer: no reset
            ((float4*)g_s2)[idx] = s;
            ((float4*)g_m2)[idx] = m;
        }
        gridbar(++gen * NCTA);
    }

    // ---- tail: GEMM2(T-1), then final lif2 + output ----
    gemm_res64<4, W2_RS, 512>(g_spk1h + ka_2, sW2, sA,
                              g_p2 + (size_t)(cta >> 3) * BATCH * 512, n0_2, 0);
    gridbar(++gen * NCTA);

    if (tid < 128) {
        int idx = cta * 128 + tid;
        float4 h = make_float4(0.f, 0.f, 0.f, 0.f);
        #pragma unroll
        for (int ks = 0; ks < 16; ks++) f4_add(h, ((const float4*)g_p2)[(size_t)ks * 16384 + idx]);
        float4 s = f4_axpy(ALPHA_C, ((float4*)g_s2)[idx], h);
        float4 m = f4_axpy(BETA_C, ((float4*)g_m2)[idx], s);
        ((float4*)out)[idx] = m;
    }
}

// ---------------- one-time prep kernels ----------------
__global__ void prep1(const float* __restrict__ inp)
{
    int g = blockIdx.x * blockDim.x + threadIdx.x;     // < 131072
    int m = g >> 10, k = g & 1023;
    float v = inp[g];
    __half hi = __float2half_rn(v);
    __half lo = __float2half_rn(v - __half2float(hi));
    size_t row = (size_t)m * KF;
    g_inh[row + k] = hi;
    g_inh[row + 1024 + k] = lo;
    g_inh[row + 2048 + k] = hi;
    g_inh[row + 3072 + k] = __float2half_rn(0.f);

    float4 z = make_float4(0.f, 0.f, 0.f, 0.f);
    if (g < 65536) { ((float4*)g_s1)[g] = z; ((float4*)g_m1)[g] = z; }
    if (g < 16384) { ((float4*)g_s2)[g] = z; ((float4*)g_m2)[g] = z; }
    if (g == 0) g_ctr = 0u;
}

__global__ void conv_w(const float* __restrict__ W, __half* __restrict__ WT, int N)
{
    __shared__ float t[32][33];
    const int k0 = blockIdx.x * 32, nb = blockIdx.y * 32;
    const int tx = threadIdx.x, ty = threadIdx.y;
    for (int i = ty; i < 32; i += 8)
        t[i][tx] = W[(size_t)(k0 + i) * N + nb + tx];
    __syncthreads();
    if (tx < 16) {
        for (int n2 = ty; n2 < 32; n2 += 8) {
            float w0 = t[2 * tx][n2], w1 = t[2 * tx + 1][n2];
            __half h0 = __float2half_rn(w0), h1 = __float2half_rn(w1);
            __half l0 = __float2half_rn(w0 - __half2float(h0));
            __half l1 = __float2half_rn(w1 - __half2float(h1));
            size_t row = (size_t)(nb + n2) * KF;
            ((__half2*)(WT + row + k0))[tx]        = __halves2half2(h0, h1);
            ((__half2*)(WT + row + 2048 + k0))[tx] = __halves2half2(l0, l1);
        }
    }
}

__global__ void conv_w0(const float* __restrict__ W, __half* __restrict__ WT)
{
    __shared__ float t[32][33];
    const int k0 = blockIdx.x * 32, nb = blockIdx.y * 32;
    const int tx = threadIdx.x, ty = threadIdx.y;
    for (int i = ty; i < 32; i += 8)
        t[i][tx] = W[(size_t)(k0 + i) * 2048 + nb + tx];
    __syncthreads();
    if (tx < 16) {
        for (int n2 = ty; n2 < 32; n2 += 8) {
            float w0 = t[2 * tx][n2], w1 = t[2 * tx + 1][n2];
            __half h0 = __float2half_rn(w0), h1 = __float2half_rn(w1);
            __half l0 = __float2half_rn(w0 - __half2float(h0));
            __half l1 = __float2half_rn(w1 - __half2float(h1));
            size_t row = (size_t)(nb + n2) * KF;
            __half2 hh = __halves2half2(h0, h1);
            ((__half2*)(WT + row + k0))[tx]        = hh;                        // seg0: hi
            ((__half2*)(WT + row + 1024 + k0))[tx] = hh;                        // seg1: hi
            ((__half2*)(WT + row + 2048 + k0))[tx] = __halves2half2(l0, l1);    // seg2: lo
            ((__half2*)(WT + row + 3072 + k0))[tx] = __halves2half2(__float2half_rn(0.f), __float2half_rn(0.f));
        }
    }
}

// ---------------- launch ----------------
extern "C" void kernel_launch(void* const* d_in, const int* in_sizes, int n_in,
                              void* d_out, int out_size)
{
    const float* inp = nullptr; const float* W0 = nullptr;
    const float* W1 = nullptr;  const float* W2 = nullptr;
    for (int i = 0; i < n_in; i++) {
        switch (in_sizes[i]) {
            case BATCH * K0: inp = (const float*)d_in[i]; break;
            case K0 * N0:    W0  = (const float*)d_in[i]; break;
            case 2048 * N1:  W1  = (const float*)d_in[i]; break;
            case 2048 * N2:  W2  = (const float*)d_in[i]; break;
        }
    }

    float* p1;
    __half *inh, *w0t, *w1t, *w2t;
    cudaGetSymbolAddress((void**)&p1,  g_p1);
    cudaGetSymbolAddress((void**)&inh, g_inh);
    cudaGetSymbolAddress((void**)&w0t, g_W0Th);
    cudaGetSymbolAddress((void**)&w1t, g_W1Th);
    cudaGetSymbolAddress((void**)&w2t, g_W2Th);

    static bool attr_done = false;
    if (!attr_done) {
        cudaFuncSetAttribute(gemm_mma<512, 2048>, cudaFuncAttributeMaxDynamicSharedMemorySize, H0_SMEM_BYTES);
        cudaFuncSetAttribute(persistent_loop, cudaFuncAttributeMaxDynamicSharedMemorySize, PERS_SMEM_BYTES);
        attr_done = true;
    }

    prep1<<<512, 256>>>(inp);                                       // #1
    conv_w0<<<dim3(32, 64), dim3(32, 8)>>>(W0, w0t);                // #2
    conv_w<<<dim3(64, 64), dim3(32, 8)>>>(W1, w1t, N1);             // #3
    conv_w<<<dim3(64, 16), dim3(32, 8)>>>(W2, w2t, N2);             // #4
    gemm_mma<512, 2048><<<dim3(16, 8), 256, H0_SMEM_BYTES>>>(inh, w0t, p1);  // #5
    persistent_loop<<<NCTA, 256, PERS_SMEM_BYTES>>>((float*)d_out); // #6
}